// round 6
// baseline (speedup 1.0000x reference)
#include <cuda_runtime.h>
#include <cuda_bf16.h>

#define NN 50000
#define EE 1000000
#define IN_DIM 128
#define HID 64
#define NL 4

// ---------------- scratch (static device globals; no allocation) -------------
__device__ float    g_h[NN * HID];     // node features (layer input / output)
__device__ float    g_hp[NN * HID];    // pre-BN layer output
__device__ float    g_A[NN * HID];
__device__ float    g_E[NN * HID];
__device__ unsigned g_Bb[NN * 32];     // Bh rows, bf16x2 packed
__device__ unsigned g_Db[NN * 32];     // Dh rows, bf16x2 packed
__device__ int      g_deg[NN];
__device__ int      g_offs[NN + 1];
__device__ int      g_cursor[NN];
__device__ int      g_csr[EE];         // src of each edge, sorted by dst
__device__ float    g_stats[2 * HID];  // per-channel sum, sumsq

__device__ __forceinline__ unsigned pack_bf16x2(float a, float b) {
    __nv_bfloat162 h = __floats2bfloat162_rn(a, b);
    return *reinterpret_cast<unsigned*>(&h);
}
__device__ __forceinline__ float2 unpack_bf16x2(unsigned u) {
    __nv_bfloat162 h = *reinterpret_cast<__nv_bfloat162*>(&u);
    return __bfloat1622float2(h);
}

// tf32 hi/lo split: x ~= hi + lo, each tf32-representable
__device__ __forceinline__ void tf32_hilo(float x, unsigned& hi, unsigned& lo) {
    unsigned h;
    asm("cvt.rna.tf32.f32 %0, %1;" : "=r"(h) : "f"(x));
    float r = x - __uint_as_float(h);
    unsigned l;
    asm("cvt.rna.tf32.f32 %0, %1;" : "=r"(l) : "f"(r));
    hi = h; lo = l;
}

__device__ __forceinline__ void mma_tf32(float* d, const unsigned* a, const unsigned* b) {
    asm("mma.sync.aligned.m16n8k8.row.col.f32.tf32.tf32.f32 "
        "{%0,%1,%2,%3}, {%4,%5,%6,%7}, {%8,%9}, {%0,%1,%2,%3};"
        : "+f"(d[0]), "+f"(d[1]), "+f"(d[2]), "+f"(d[3])
        : "r"(a[0]), "r"(a[1]), "r"(a[2]), "r"(a[3]), "r"(b[0]), "r"(b[1]));
}

// ---------------- sort edges by dst: hist -> scan -> scatter ------------------
__global__ void k_clear_deg() {
    int i = blockIdx.x * blockDim.x + threadIdx.x;
    if (i < NN) g_deg[i] = 0;
}

__global__ void k_hist(const int* __restrict__ ei) {
    int e = blockIdx.x * blockDim.x + threadIdx.x;
    if (e < EE) {
        int d = ei[EE + e];
        if (d >= 0 && d < NN) atomicAdd(&g_deg[d], 1);
    }
}

__global__ void k_scan() {  // single block, 1024 threads
    __shared__ int wsum[32];
    __shared__ int carry_sh;
    int t = threadIdx.x;
    if (t == 0) carry_sh = 0;
    __syncthreads();
    for (int base = 0; base < NN; base += 1024) {
        int i = base + t;
        int v = (i < NN) ? g_deg[i] : 0;
        int x = v;
        #pragma unroll
        for (int o = 1; o < 32; o <<= 1) {
            int y = __shfl_up_sync(0xffffffffu, x, o);
            if ((t & 31) >= o) x += y;
        }
        if ((t & 31) == 31) wsum[t >> 5] = x;
        __syncthreads();
        if (t < 32) {
            int w = wsum[t];
            #pragma unroll
            for (int o = 1; o < 32; o <<= 1) {
                int y = __shfl_up_sync(0xffffffffu, w, o);
                if (t >= o) w += y;
            }
            wsum[t] = w;
        }
        __syncthreads();
        int incl = x + ((t >= 32) ? wsum[(t >> 5) - 1] : 0);
        int carry = carry_sh;
        if (i < NN) {
            g_offs[i + 1]  = carry + incl;
            g_cursor[i]    = carry + incl - v;
        }
        __syncthreads();
        if (t == 0) carry_sh = carry + wsum[31];
        __syncthreads();
    }
    if (t == 0) g_offs[0] = 0;
}

__global__ void k_scatter(const int* __restrict__ ei) {
    int e = blockIdx.x * blockDim.x + threadIdx.x;
    if (e < EE) {
        int d = ei[EE + e];
        int s = ei[e];
        if (d >= 0 && d < NN) {
            int pos = atomicAdd(&g_cursor[d], 1);
            if (pos >= 0 && pos < EE) g_csr[pos] = s;
        }
    }
}

// ---------------- embed: h = feature @ emb_w + emb_b (SIMT fp32) -------------
__global__ __launch_bounds__(256) void k_embed(const float* __restrict__ X,
                                               const float* __restrict__ W,
                                               const float* __restrict__ bias) {
    __shared__ float Ws[IN_DIM * HID];   // 32KB
    __shared__ float Xs[32 * IN_DIM];    // 16KB
    int t = threadIdx.x;
    int m0 = blockIdx.x * 32;
    for (int idx = t; idx < IN_DIM * HID; idx += 256) Ws[idx] = W[idx];
    for (int idx = t; idx < 32 * IN_DIM; idx += 256) {
        int m = m0 + (idx >> 7);
        Xs[idx] = (m < NN) ? X[m * IN_DIM + (idx & 127)] : 0.f;
    }
    __syncthreads();
    int tx = t & 31, ty = t >> 5;
    int c0 = tx * 2, r0 = ty * 4;
    float acc[4][2];
    #pragma unroll
    for (int i = 0; i < 4; i++) { acc[i][0] = 0.f; acc[i][1] = 0.f; }
    #pragma unroll 8
    for (int k = 0; k < IN_DIM; k++) {
        float2 w = *(const float2*)&Ws[k * HID + c0];
        #pragma unroll
        for (int i = 0; i < 4; i++) {
            float x = Xs[(r0 + i) * IN_DIM + k];
            acc[i][0] += x * w.x;
            acc[i][1] += x * w.y;
        }
    }
    float b0 = bias[c0], b1 = bias[c0 + 1];
    #pragma unroll
    for (int i = 0; i < 4; i++) {
        int m = m0 + r0 + i;
        if (m < NN) {
            g_h[m * HID + c0]     = acc[i][0] + b0;
            g_h[m * HID + c0 + 1] = acc[i][1] + b1;
        }
    }
}

// ---------------- layer linears: tf32 MMA, hi/lo pre-split in smem ------------
// Block 256 thr (8 warps), 64 rows x 256 cols (A|B|D|E).
// Outer loop: half (128 cols). Inner: K chunk of 32 (2 chunks).
// smem: Xh/Xl 8KB each + Wh/Wl 16KB each = 48KB exactly.
// X swizzle: (r,k)->r*32+(k^((r&7)<<2)).  W swizzle: (k,c)->k*128+(c^((k&3)<<3)).
__global__ __launch_bounds__(256) void k_abde(
    const float* __restrict__ Aw, const float* __restrict__ Bw,
    const float* __restrict__ Dw, const float* __restrict__ Ew,
    const float* __restrict__ Ab, const float* __restrict__ Bb,
    const float* __restrict__ Db, const float* __restrict__ Eb) {
    __shared__ unsigned Xh[64 * 32], Xl[64 * 32];
    __shared__ unsigned Wh[32 * 128], Wl[32 * 128];
    int t = threadIdx.x;
    int m0 = blockIdx.x * 64;
    int lane = t & 31, w = t >> 5;
    int g = lane >> 2, tig = lane & 3;
    int mt = w & 3, nh = w >> 2;        // nh in {0,1}
    int r0 = mt * 16 + g, r1 = r0 + 8;

    #pragma unroll
    for (int half = 0; half < 2; half++) {
        float acc[8][4];
        #pragma unroll
        for (int i = 0; i < 8; i++)
            #pragma unroll
            for (int j = 0; j < 4; j++) acc[i][j] = 0.f;

        #pragma unroll
        for (int kc = 0; kc < 2; kc++) {
            // stage X chunk: rows 0..63, k in [kc*32, kc*32+32)
            for (int idx = t; idx < 64 * 8; idx += 256) {
                int r = idx >> 3, c4 = (idx & 7) * 4;
                float4 v = make_float4(0.f, 0.f, 0.f, 0.f);
                if (m0 + r < NN)
                    v = *(const float4*)&g_h[(m0 + r) * HID + kc * 32 + c4];
                unsigned h0, l0, h1, l1, h2, l2, h3, l3;
                tf32_hilo(v.x, h0, l0); tf32_hilo(v.y, h1, l1);
                tf32_hilo(v.z, h2, l2); tf32_hilo(v.w, h3, l3);
                int s = r * 32 + (c4 ^ ((r & 7) << 2));
                *(uint4*)&Xh[s] = make_uint4(h0, h1, h2, h3);
                *(uint4*)&Xl[s] = make_uint4(l0, l1, l2, l3);
            }
            // stage W chunk: k in [kc*32,+32), cols [half*128,+128) of concat
            for (int idx = t; idx < 32 * 32; idx += 256) {
                int k = idx >> 5, c4 = (idx & 31) * 4;
                int gc = half * 128 + c4;
                int sel = gc >> 6;
                const float* W = (sel == 0) ? Aw : (sel == 1) ? Bw
                               : (sel == 2) ? Dw : Ew;
                float4 v = *(const float4*)&W[(kc * 32 + k) * HID + (gc & 63)];
                unsigned h0, l0, h1, l1, h2, l2, h3, l3;
                tf32_hilo(v.x, h0, l0); tf32_hilo(v.y, h1, l1);
                tf32_hilo(v.z, h2, l2); tf32_hilo(v.w, h3, l3);
                int s = k * 128 + (c4 ^ ((k & 3) << 3));
                *(uint4*)&Wh[s] = make_uint4(h0, h1, h2, h3);
                *(uint4*)&Wl[s] = make_uint4(l0, l1, l2, l3);
            }
            __syncthreads();

            #pragma unroll
            for (int ks = 0; ks < 4; ks++) {
                int k0 = ks * 8 + tig, k1 = k0 + 4;
                int sa0 = r0 * 32 + (k0 ^ ((r0 & 7) << 2));
                int sa1 = r1 * 32 + (k0 ^ ((r1 & 7) << 2));
                int sa2 = r0 * 32 + (k1 ^ ((r0 & 7) << 2));
                int sa3 = r1 * 32 + (k1 ^ ((r1 & 7) << 2));
                unsigned ah[4] = {Xh[sa0], Xh[sa1], Xh[sa2], Xh[sa3]};
                unsigned al[4] = {Xl[sa0], Xl[sa1], Xl[sa2], Xl[sa3]};
                #pragma unroll
                for (int nt = 0; nt < 8; nt++) {
                    int c = nh * 64 + nt * 8 + g;
                    int sb0 = k0 * 128 + (c ^ ((k0 & 3) << 3));
                    int sb1 = k1 * 128 + (c ^ ((k1 & 3) << 3));
                    unsigned bh[2] = {Wh[sb0], Wh[sb1]};
                    unsigned bl[2] = {Wl[sb0], Wl[sb1]};
                    mma_tf32(acc[nt], ah, bh);
                    mma_tf32(acc[nt], al, bh);
                    mma_tf32(acc[nt], ah, bl);
                }
            }
            __syncthreads();
        }

        // store: warp's 64 cols = one matrix. sel = half*2 + nh
        int sel = half * 2 + nh;
        const float* bp = (sel == 0) ? Ab : (sel == 1) ? Bb : (sel == 2) ? Db : Eb;
        int mra = m0 + mt * 16 + g, mrb = mra + 8;
        if (sel == 0 || sel == 3) {
            float* Y = (sel == 0) ? g_A : g_E;
            #pragma unroll
            for (int nt = 0; nt < 8; nt++) {
                int cc = nt * 8 + 2 * tig;
                float b0v = bp[cc], b1v = bp[cc + 1];
                if (mra < NN) {
                    float2 v = make_float2(acc[nt][0] + b0v, acc[nt][1] + b1v);
                    *(float2*)&Y[mra * HID + cc] = v;
                }
                if (mrb < NN) {
                    float2 v = make_float2(acc[nt][2] + b0v, acc[nt][3] + b1v);
                    *(float2*)&Y[mrb * HID + cc] = v;
                }
            }
        } else {
            unsigned* Y = (sel == 1) ? g_Bb : g_Db;
            #pragma unroll
            for (int nt = 0; nt < 8; nt++) {
                int cc = nt * 8 + 2 * tig;
                float b0v = bp[cc], b1v = bp[cc + 1];
                int wc = nt * 4 + tig;
                if (mra < NN) Y[mra * 32 + wc] = pack_bf16x2(acc[nt][0] + b0v, acc[nt][1] + b1v);
                if (mrb < NN) Y[mrb * 32 + wc] = pack_bf16x2(acc[nt][2] + b0v, acc[nt][3] + b1v);
            }
        }
        __syncthreads();   // before smem reuse in next half
    }
}

// ---------------- edge aggregation + fused BN stats ---------------------------
__global__ __launch_bounds__(256) void k_agg() {
    __shared__ float red_s[8][64], red_q[8][64];
    int w = threadIdx.x >> 5, lane = threadIdx.x & 31;
    int base = (blockIdx.x * 8 + w) * 4;
    float sx = 0.f, sy = 0.f, qx = 0.f, qy = 0.f;
    #pragma unroll 1
    for (int i = 0; i < 4; i++) {
        int gw = base + i;
        if (gw >= NN) break;
        int s0 = g_offs[gw], s1 = g_offs[gw + 1];
        int off = gw * HID + lane * 2;
        float2 el = *(const float2*)&g_E[off];
        float nx = 0.f, ny = 0.f, dx = 0.f, dy = 0.f;
        int k = s0;
        for (; k + 1 < s1; k += 2) {
            int sa = g_csr[k], sb = g_csr[k + 1];
            unsigned ua_d = g_Db[sa * 32 + lane];
            unsigned ua_b = g_Bb[sa * 32 + lane];
            unsigned ub_d = g_Db[sb * 32 + lane];
            unsigned ub_b = g_Bb[sb * 32 + lane];
            float2 da = unpack_bf16x2(ua_d), ba = unpack_bf16x2(ua_b);
            float2 db = unpack_bf16x2(ub_d), bb = unpack_bf16x2(ub_b);
            float s0x = 1.f / (1.f + __expf(-(da.x + el.x)));
            float s0y = 1.f / (1.f + __expf(-(da.y + el.y)));
            float s1x = 1.f / (1.f + __expf(-(db.x + el.x)));
            float s1y = 1.f / (1.f + __expf(-(db.y + el.y)));
            nx += s0x * ba.x + s1x * bb.x;
            ny += s0y * ba.y + s1y * bb.y;
            dx += s0x + s1x;
            dy += s0y + s1y;
        }
        if (k < s1) {
            int sa = g_csr[k];
            float2 da = unpack_bf16x2(g_Db[sa * 32 + lane]);
            float2 ba = unpack_bf16x2(g_Bb[sa * 32 + lane]);
            float ssx = 1.f / (1.f + __expf(-(da.x + el.x)));
            float ssy = 1.f / (1.f + __expf(-(da.y + el.y)));
            nx += ssx * ba.x; ny += ssy * ba.y;
            dx += ssx;        dy += ssy;
        }
        float2 aa = *(const float2*)&g_A[off];
        float ox = aa.x + nx / (dx + 1e-6f);
        float oy = aa.y + ny / (dy + 1e-6f);
        *(float2*)&g_hp[off] = make_float2(ox, oy);
        sx += ox; sy += oy; qx += ox * ox; qy += oy * oy;
    }
    red_s[w][lane * 2] = sx;  red_s[w][lane * 2 + 1] = sy;
    red_q[w][lane * 2] = qx;  red_q[w][lane * 2 + 1] = qy;
    __syncthreads();
    int t = threadIdx.x;
    if (t < 64) {
        float s = 0.f, q = 0.f;
        #pragma unroll
        for (int ww = 0; ww < 8; ww++) { s += red_s[ww][t]; q += red_q[ww][t]; }
        atomicAdd(&g_stats[t], s);
        atomicAdd(&g_stats[HID + t], q);
    }
}

// ---------------- BN/ReLU/residual --------------------------------------------
__global__ void k_clear_stats() {
    int t = threadIdx.x;
    if (t < 2 * HID) g_stats[t] = 0.f;
}

__global__ __launch_bounds__(256) void k_bn(const float* __restrict__ gamma,
                                            const float* __restrict__ beta,
                                            float* __restrict__ out,
                                            int write_out) {
    int idx = blockIdx.x * blockDim.x + threadIdx.x;
    if (idx >= NN * HID) return;
    int c = idx & 63;
    const float invN = 1.f / (float)NN;
    float mu  = g_stats[c] * invN;
    float var = g_stats[HID + c] * invN - mu * mu;
    float xn = (g_hp[idx] - mu) * rsqrtf(var + 1e-5f);
    float v = gamma[c] * xn + beta[c];
    v = fmaxf(v, 0.f);
    float r = g_h[idx] + v;
    g_h[idx] = r;
    if (write_out) out[idx] = r;
}

// ---------------- launch ------------------------------------------------------
extern "C" void kernel_launch(void* const* d_in, const int* in_sizes, int n_in,
                              void* d_out, int out_size) {
    const float* feature = (const float*)d_in[0];
    const int*   ei      = (const int*)d_in[1];     // int32 (JAX x64 disabled)
    const float* emb_w   = (const float*)d_in[2];
    const float* emb_b   = (const float*)d_in[3];
    const float* Aw      = (const float*)d_in[4];
    const float* Ab      = (const float*)d_in[5];
    const float* Bw      = (const float*)d_in[6];
    const float* Bb      = (const float*)d_in[7];
    const float* Dw      = (const float*)d_in[8];
    const float* Db      = (const float*)d_in[9];
    const float* Ew      = (const float*)d_in[10];
    const float* Eb      = (const float*)d_in[11];
    const float* gamma   = (const float*)d_in[12];
    const float* beta    = (const float*)d_in[13];
    float* out = (float*)d_out;

    k_clear_deg<<<(NN + 255) / 256, 256>>>();
    k_hist<<<(EE + 255) / 256, 256>>>(ei);
    k_scan<<<1, 1024>>>();
    k_scatter<<<(EE + 255) / 256, 256>>>(ei);

    k_embed<<<(NN + 31) / 32, 256>>>(feature, emb_w, emb_b);

    for (int l = 0; l < NL; l++) {
        k_abde<<<(NN + 63) / 64, 256>>>(
            Aw + l * HID * HID, Bw + l * HID * HID,
            Dw + l * HID * HID, Ew + l * HID * HID,
            Ab + l * HID, Bb + l * HID, Db + l * HID, Eb + l * HID);
        k_clear_stats<<<1, 128>>>();
        k_agg<<<(NN + 31) / 32, 256>>>();
        k_bn<<<(NN * HID + 255) / 256, 256>>>(gamma + l * HID, beta + l * HID,
                                              out, (l == NL - 1) ? 1 : 0);
    }
}

// round 7
// speedup vs baseline: 1.3111x; 1.3111x over previous
#include <cuda_runtime.h>
#include <cuda_bf16.h>

#define NN 50000
#define EE 1000000
#define IN_DIM 128
#define HID 64
#define NL 4
#define SCAN_B 196   // ceil(NN/256)

// ---------------- scratch (static device globals; no allocation) -------------
__device__ float    g_h[NN * HID];     // node features (layer input / output)
__device__ float    g_hp[NN * HID];    // pre-BN layer output
__device__ float    g_A[NN * HID];
__device__ float    g_E[NN * HID];
__device__ unsigned g_BD[NN * 64];     // interleaved: word 2p = D-pack(pair p), 2p+1 = B-pack
__device__ int      g_deg[NN];
__device__ int      g_offs[NN + 1];
__device__ int      g_cursor[NN];
__device__ int      g_csr[EE];         // src of each edge, sorted by dst
__device__ float    g_stats[2 * HID];  // per-channel sum, sumsq
__device__ int      g_bsum[256];
__device__ int      g_bpre[256];

__device__ __forceinline__ unsigned pack_bf16x2(float a, float b) {
    __nv_bfloat162 h = __floats2bfloat162_rn(a, b);
    return *reinterpret_cast<unsigned*>(&h);
}
__device__ __forceinline__ float2 unpack_bf16x2(unsigned u) {
    __nv_bfloat162 h = *reinterpret_cast<__nv_bfloat162*>(&u);
    return __bfloat1622float2(h);
}
__device__ __forceinline__ float sigmoid_fast(float x) {
    float t;
    asm("tanh.approx.f32 %0, %1;" : "=f"(t) : "f"(0.5f * x));
    return fmaf(t, 0.5f, 0.5f);
}

// ---------------- CSR build: hist -> 3-kernel scan -> scatter -----------------
__global__ void k_clear_deg() {
    int i = blockIdx.x * blockDim.x + threadIdx.x;
    if (i < NN) g_deg[i] = 0;
}

__global__ void k_hist(const int* __restrict__ ei) {
    int e = blockIdx.x * blockDim.x + threadIdx.x;
    if (e < EE) {
        int d = ei[EE + e];
        if (d >= 0 && d < NN) atomicAdd(&g_deg[d], 1);
    }
}

__global__ void k_bsum() {   // per-block sums of deg (256 nodes/block)
    __shared__ int ws[8];
    int t = threadIdx.x, b = blockIdx.x;
    int i = b * 256 + t;
    int v = (i < NN) ? g_deg[i] : 0;
    #pragma unroll
    for (int o = 16; o; o >>= 1) v += __shfl_down_sync(0xffffffffu, v, o);
    if ((t & 31) == 0) ws[t >> 5] = v;
    __syncthreads();
    if (t == 0) {
        int s = 0;
        #pragma unroll
        for (int j = 0; j < 8; j++) s += ws[j];
        g_bsum[b] = s;
    }
}

__global__ void k_bscan() {  // 1 block: exclusive scan of 196 block sums
    __shared__ int ws[8];
    int t = threadIdx.x;
    int v = (t < SCAN_B) ? g_bsum[t] : 0;
    int lane = t & 31, wid = t >> 5;
    int x = v;
    #pragma unroll
    for (int o = 1; o < 32; o <<= 1) {
        int y = __shfl_up_sync(0xffffffffu, x, o);
        if (lane >= o) x += y;
    }
    if (lane == 31) ws[wid] = x;
    __syncthreads();
    if (t < 8) {
        int w = ws[t];
        #pragma unroll
        for (int o = 1; o < 8; o <<= 1) {
            int y = __shfl_up_sync(0xffu, w, o);
            if (t >= o) w += y;
        }
        ws[t] = w;
    }
    __syncthreads();
    int incl = x + (wid ? ws[wid - 1] : 0);
    g_bpre[t] = incl - v;   // exclusive prefix
}

__global__ void k_offs() {   // per-block local scan + block prefix -> offs/cursor
    __shared__ int ws[8];
    int t = threadIdx.x, b = blockIdx.x;
    int i = b * 256 + t;
    int v = (i < NN) ? g_deg[i] : 0;
    int lane = t & 31, wid = t >> 5;
    int x = v;
    #pragma unroll
    for (int o = 1; o < 32; o <<= 1) {
        int y = __shfl_up_sync(0xffffffffu, x, o);
        if (lane >= o) x += y;
    }
    if (lane == 31) ws[wid] = x;
    __syncthreads();
    if (t < 8) {
        int w = ws[t];
        #pragma unroll
        for (int o = 1; o < 8; o <<= 1) {
            int y = __shfl_up_sync(0xffu, w, o);
            if (t >= o) w += y;
        }
        ws[t] = w;
    }
    __syncthreads();
    int incl = x + (wid ? ws[wid - 1] : 0);
    int base = g_bpre[b];
    if (i < NN) {
        g_offs[i + 1] = base + incl;
        g_cursor[i]   = base + incl - v;
    }
    if (i == 0) g_offs[0] = 0;
}

__global__ void k_scatter(const int* __restrict__ ei) {
    int e = blockIdx.x * blockDim.x + threadIdx.x;
    if (e < EE) {
        int d = ei[EE + e];
        int s = ei[e];
        if (d >= 0 && d < NN) {
            int pos = atomicAdd(&g_cursor[d], 1);
            if (pos >= 0 && pos < EE) g_csr[pos] = s;
        }
    }
}

// ---------------- embed: h = feature @ emb_w + emb_b (SIMT fp32) -------------
__global__ __launch_bounds__(256) void k_embed(const float* __restrict__ X,
                                               const float* __restrict__ W,
                                               const float* __restrict__ bias) {
    __shared__ float Ws[IN_DIM * HID];   // 32KB
    __shared__ float Xs[32 * IN_DIM];    // 16KB
    int t = threadIdx.x;
    int m0 = blockIdx.x * 32;
    for (int idx = t; idx < IN_DIM * HID; idx += 256) Ws[idx] = W[idx];
    for (int idx = t; idx < 32 * IN_DIM; idx += 256) {
        int m = m0 + (idx >> 7);
        Xs[idx] = (m < NN) ? X[m * IN_DIM + (idx & 127)] : 0.f;
    }
    __syncthreads();
    int tx = t & 31, ty = t >> 5;
    int c0 = tx * 2, r0 = ty * 4;
    float acc[4][2];
    #pragma unroll
    for (int i = 0; i < 4; i++) { acc[i][0] = 0.f; acc[i][1] = 0.f; }
    #pragma unroll 8
    for (int k = 0; k < IN_DIM; k++) {
        float2 w = *(const float2*)&Ws[k * HID + c0];
        #pragma unroll
        for (int i = 0; i < 4; i++) {
            float x = Xs[(r0 + i) * IN_DIM + k];
            acc[i][0] += x * w.x;
            acc[i][1] += x * w.y;
        }
    }
    float b0 = bias[c0], b1 = bias[c0 + 1];
    #pragma unroll
    for (int i = 0; i < 4; i++) {
        int m = m0 + r0 + i;
        if (m < NN) {
            g_h[m * HID + c0]     = acc[i][0] + b0;
            g_h[m * HID + c0 + 1] = acc[i][1] + b1;
        }
    }
}

// ---------------- layer linears (R4 SIMT version, interleaved B/D store) -----
__global__ __launch_bounds__(256) void k_abde(
    const float* __restrict__ Aw, const float* __restrict__ Bw,
    const float* __restrict__ Dw, const float* __restrict__ Ew,
    const float* __restrict__ Ab, const float* __restrict__ Bb,
    const float* __restrict__ Db, const float* __restrict__ Eb) {
    __shared__ float Ws[HID * 128];   // 32KB, k-major: 128 cols of current half
    __shared__ float Xs[64 * HID];    // 16KB, row-major
    int t = threadIdx.x;
    int m0 = blockIdx.x * 64;

    for (int idx = t; idx < 64 * (HID / 4); idx += 256) {
        int m = m0 + idx / (HID / 4);
        float4 v = make_float4(0.f, 0.f, 0.f, 0.f);
        if (m < NN) v = *(const float4*)&g_h[m * HID + (idx % (HID / 4)) * 4];
        *(float4*)&Xs[idx * 4] = v;
    }

    const int tx = t & 31, ty = t >> 5;
    const int c0 = tx * 4, r0 = ty * 8;

    #pragma unroll
    for (int half = 0; half < 2; half++) {
        for (int idx = t; idx < HID * 128; idx += 256) {
            int k = idx >> 7, c = idx & 127;
            int gc = half * 128 + c;
            int sel = gc >> 6;
            const float* W = (sel == 0) ? Aw : (sel == 1) ? Bw : (sel == 2) ? Dw : Ew;
            Ws[idx] = W[k * HID + (gc & 63)];
        }
        __syncthreads();

        float acc[8][4];
        #pragma unroll
        for (int i = 0; i < 8; i++)
            #pragma unroll
            for (int j = 0; j < 4; j++) acc[i][j] = 0.f;

        #pragma unroll 4
        for (int k0 = 0; k0 < HID; k0 += 4) {
            float4 xv[8];
            #pragma unroll
            for (int i = 0; i < 8; i++)
                xv[i] = *(const float4*)&Xs[(r0 + i) * HID + k0];
            #pragma unroll
            for (int kk = 0; kk < 4; kk++) {
                float4 w = *(const float4*)&Ws[(k0 + kk) * 128 + c0];
                #pragma unroll
                for (int i = 0; i < 8; i++) {
                    float x = (kk == 0) ? xv[i].x : (kk == 1) ? xv[i].y
                            : (kk == 2) ? xv[i].z : xv[i].w;
                    acc[i][0] += x * w.x; acc[i][1] += x * w.y;
                    acc[i][2] += x * w.z; acc[i][3] += x * w.w;
                }
            }
        }

        int gc0 = half * 128 + c0;
        int sel = gc0 >> 6, cc = gc0 & 63;
        const float* bp = (sel == 0) ? Ab : (sel == 1) ? Bb : (sel == 2) ? Db : Eb;
        float b0 = bp[cc], b1 = bp[cc + 1], b2 = bp[cc + 2], b3 = bp[cc + 3];

        if (sel == 0 || sel == 3) {            // A or E: fp32
            float* Y = (sel == 0) ? g_A : g_E;
            #pragma unroll
            for (int i = 0; i < 8; i++) {
                int m = m0 + r0 + i;
                if (m < NN) {
                    float4 v = make_float4(acc[i][0] + b0, acc[i][1] + b1,
                                           acc[i][2] + b2, acc[i][3] + b3);
                    *(float4*)&Y[m * HID + cc] = v;
                }
            }
        } else {                               // B or D: bf16x2 interleaved
            int boff = (sel == 1) ? 1 : 0;     // B at odd words, D at even
            #pragma unroll
            for (int i = 0; i < 8; i++) {
                int m = m0 + r0 + i;
                if (m < NN) {
                    int base = m * 64 + cc + boff;  // 2*(cc/2) == cc (cc mult of 4)
                    g_BD[base]     = pack_bf16x2(acc[i][0] + b0, acc[i][1] + b1);
                    g_BD[base + 2] = pack_bf16x2(acc[i][2] + b2, acc[i][3] + b3);
                }
            }
        }
        __syncthreads();
    }
}

// ---------------- edge aggregation + fused BN stats ---------------------------
// 8 warps/block, warp handles 4 nodes; one LDG.64 per src per lane (D,B pair).
__global__ __launch_bounds__(256) void k_agg() {
    __shared__ float red_s[8][64], red_q[8][64];
    int w = threadIdx.x >> 5, lane = threadIdx.x & 31;
    int base = (blockIdx.x * 8 + w) * 4;
    float sx = 0.f, sy = 0.f, qx = 0.f, qy = 0.f;
    #pragma unroll 1
    for (int i = 0; i < 4; i++) {
        int gw = base + i;
        if (gw >= NN) break;
        int s0 = g_offs[gw], s1 = g_offs[gw + 1];
        int off = gw * HID + lane * 2;
        float2 el = *(const float2*)&g_E[off];
        float nx = 0.f, ny = 0.f, dx = 0.f, dy = 0.f;
        int k = s0;
        for (; k + 1 < s1; k += 2) {
            int sa = g_csr[k], sb = g_csr[k + 1];
            uint2 va = *(const uint2*)&g_BD[sa * 64 + lane * 2];
            uint2 vb = *(const uint2*)&g_BD[sb * 64 + lane * 2];
            float2 da = unpack_bf16x2(va.x), ba = unpack_bf16x2(va.y);
            float2 db = unpack_bf16x2(vb.x), bb = unpack_bf16x2(vb.y);
            float s0x = sigmoid_fast(da.x + el.x);
            float s0y = sigmoid_fast(da.y + el.y);
            float s1x = sigmoid_fast(db.x + el.x);
            float s1y = sigmoid_fast(db.y + el.y);
            nx += s0x * ba.x + s1x * bb.x;
            ny += s0y * ba.y + s1y * bb.y;
            dx += s0x + s1x;
            dy += s0y + s1y;
        }
        if (k < s1) {
            int sa = g_csr[k];
            uint2 va = *(const uint2*)&g_BD[sa * 64 + lane * 2];
            float2 da = unpack_bf16x2(va.x), ba = unpack_bf16x2(va.y);
            float ssx = sigmoid_fast(da.x + el.x);
            float ssy = sigmoid_fast(da.y + el.y);
            nx += ssx * ba.x; ny += ssy * ba.y;
            dx += ssx;        dy += ssy;
        }
        float2 aa = *(const float2*)&g_A[off];
        float ox = aa.x + nx / (dx + 1e-6f);
        float oy = aa.y + ny / (dy + 1e-6f);
        *(float2*)&g_hp[off] = make_float2(ox, oy);
        sx += ox; sy += oy; qx += ox * ox; qy += oy * oy;
    }
    red_s[w][lane * 2] = sx;  red_s[w][lane * 2 + 1] = sy;
    red_q[w][lane * 2] = qx;  red_q[w][lane * 2 + 1] = qy;
    __syncthreads();
    int t = threadIdx.x;
    if (t < 64) {
        float s = 0.f, q = 0.f;
        #pragma unroll
        for (int ww = 0; ww < 8; ww++) { s += red_s[ww][t]; q += red_q[ww][t]; }
        atomicAdd(&g_stats[t], s);
        atomicAdd(&g_stats[HID + t], q);
    }
}

// ---------------- BN/ReLU/residual --------------------------------------------
__global__ void k_clear_stats() {
    int t = threadIdx.x;
    if (t < 2 * HID) g_stats[t] = 0.f;
}

__global__ __launch_bounds__(256) void k_bn(const float* __restrict__ gamma,
                                            const float* __restrict__ beta,
                                            float* __restrict__ out,
                                            int write_out) {
    int idx = blockIdx.x * blockDim.x + threadIdx.x;
    if (idx >= NN * HID) return;
    int c = idx & 63;
    const float invN = 1.f / (float)NN;
    float mu  = g_stats[c] * invN;
    float var = g_stats[HID + c] * invN - mu * mu;
    float xn = (g_hp[idx] - mu) * rsqrtf(var + 1e-5f);
    float v = gamma[c] * xn + beta[c];
    v = fmaxf(v, 0.f);
    float r = g_h[idx] + v;
    g_h[idx] = r;
    if (write_out) out[idx] = r;
}

// ---------------- launch ------------------------------------------------------
extern "C" void kernel_launch(void* const* d_in, const int* in_sizes, int n_in,
                              void* d_out, int out_size) {
    const float* feature = (const float*)d_in[0];
    const int*   ei      = (const int*)d_in[1];     // int32 (JAX x64 disabled)
    const float* emb_w   = (const float*)d_in[2];
    const float* emb_b   = (const float*)d_in[3];
    const float* Aw      = (const float*)d_in[4];
    const float* Ab      = (const float*)d_in[5];
    const float* Bw      = (const float*)d_in[6];
    const float* Bb      = (const float*)d_in[7];
    const float* Dw      = (const float*)d_in[8];
    const float* Db      = (const float*)d_in[9];
    const float* Ew      = (const float*)d_in[10];
    const float* Eb      = (const float*)d_in[11];
    const float* gamma   = (const float*)d_in[12];
    const float* beta    = (const float*)d_in[13];
    float* out = (float*)d_out;

    k_clear_deg<<<(NN + 255) / 256, 256>>>();
    k_hist<<<(EE + 255) / 256, 256>>>(ei);
    k_bsum<<<SCAN_B, 256>>>();
    k_bscan<<<1, 256>>>();
    k_offs<<<SCAN_B, 256>>>();
    k_scatter<<<(EE + 255) / 256, 256>>>(ei);

    k_embed<<<(NN + 31) / 32, 256>>>(feature, emb_w, emb_b);

    for (int l = 0; l < NL; l++) {
        k_abde<<<(NN + 63) / 64, 256>>>(
            Aw + l * HID * HID, Bw + l * HID * HID,
            Dw + l * HID * HID, Ew + l * HID * HID,
            Ab + l * HID, Bb + l * HID, Db + l * HID, Eb + l * HID);
        k_clear_stats<<<1, 128>>>();
        k_agg<<<(NN + 31) / 32, 256>>>();
        k_bn<<<(NN * HID + 255) / 256, 256>>>(gamma + l * HID, beta + l * HID,
                                              out, (l == NL - 1) ? 1 : 0);
    }
}

// round 8
// speedup vs baseline: 1.3837x; 1.0554x over previous
#include <cuda_runtime.h>
#include <cuda_bf16.h>

#define NN 50000
#define EE 1000000
#define IN_DIM 128
#define HID 64
#define NL 4
#define SCAN_B 196   // ceil(NN/256)

// ---------------- scratch (static device globals; no allocation) -------------
__device__ float    g_h[NN * HID];     // node features (residual-applied)
__device__ float    g_hp[NN * HID];    // pre-BN layer output
__device__ float    g_A[NN * HID];
__device__ float    g_E[NN * HID];
__device__ unsigned g_BD[NN * 64];     // interleaved: even word = D pack, odd = B pack
__device__ int      g_deg[NN];
__device__ int      g_offs[NN + 1];
__device__ int      g_cursor[NN];
__device__ int      g_csr[EE];
__device__ float    g_stats[NL][2 * HID];  // per-layer: sum, sumsq
__device__ int      g_bsum[256];
__device__ int      g_bpre[256];

__device__ __forceinline__ unsigned pack_bf16x2(float a, float b) {
    __nv_bfloat162 h = __floats2bfloat162_rn(a, b);
    return *reinterpret_cast<unsigned*>(&h);
}
__device__ __forceinline__ float2 unpack_bf16x2(unsigned u) {
    __nv_bfloat162 h = *reinterpret_cast<__nv_bfloat162*>(&u);
    return __bfloat1622float2(h);
}
__device__ __forceinline__ float sigmoid_fast(float x) {
    float t;
    asm("tanh.approx.f32 %0, %1;" : "=f"(t) : "f"(0.5f * x));
    return fmaf(t, 0.5f, 0.5f);
}

// ---------------- CSR build ----------------------------------------------------
__global__ void k_clear_deg() {
    int i = blockIdx.x * blockDim.x + threadIdx.x;
    if (i < NN) g_deg[i] = 0;
    if (i < NL * 2 * HID) ((float*)g_stats)[i] = 0.f;   // clear all stat buffers
}

__global__ void k_hist(const int* __restrict__ ei) {
    int e = blockIdx.x * blockDim.x + threadIdx.x;
    if (e < EE) {
        int d = ei[EE + e];
        if (d >= 0 && d < NN) atomicAdd(&g_deg[d], 1);
    }
}

__global__ void k_bsum() {
    __shared__ int ws[8];
    int t = threadIdx.x, b = blockIdx.x;
    int i = b * 256 + t;
    int v = (i < NN) ? g_deg[i] : 0;
    #pragma unroll
    for (int o = 16; o; o >>= 1) v += __shfl_down_sync(0xffffffffu, v, o);
    if ((t & 31) == 0) ws[t >> 5] = v;
    __syncthreads();
    if (t == 0) {
        int s = 0;
        #pragma unroll
        for (int j = 0; j < 8; j++) s += ws[j];
        g_bsum[b] = s;
    }
}

__global__ void k_bscan() {
    __shared__ int ws[8];
    int t = threadIdx.x;
    int v = (t < SCAN_B) ? g_bsum[t] : 0;
    int lane = t & 31, wid = t >> 5;
    int x = v;
    #pragma unroll
    for (int o = 1; o < 32; o <<= 1) {
        int y = __shfl_up_sync(0xffffffffu, x, o);
        if (lane >= o) x += y;
    }
    if (lane == 31) ws[wid] = x;
    __syncthreads();
    if (t < 8) {
        int w = ws[t];
        #pragma unroll
        for (int o = 1; o < 8; o <<= 1) {
            int y = __shfl_up_sync(0xffu, w, o);
            if (t >= o) w += y;
        }
        ws[t] = w;
    }
    __syncthreads();
    int incl = x + (wid ? ws[wid - 1] : 0);
    g_bpre[t] = incl - v;
}

__global__ void k_offs() {
    __shared__ int ws[8];
    int t = threadIdx.x, b = blockIdx.x;
    int i = b * 256 + t;
    int v = (i < NN) ? g_deg[i] : 0;
    int lane = t & 31, wid = t >> 5;
    int x = v;
    #pragma unroll
    for (int o = 1; o < 32; o <<= 1) {
        int y = __shfl_up_sync(0xffffffffu, x, o);
        if (lane >= o) x += y;
    }
    if (lane == 31) ws[wid] = x;
    __syncthreads();
    if (t < 8) {
        int w = ws[t];
        #pragma unroll
        for (int o = 1; o < 8; o <<= 1) {
            int y = __shfl_up_sync(0xffu, w, o);
            if (t >= o) w += y;
        }
        ws[t] = w;
    }
    __syncthreads();
    int incl = x + (wid ? ws[wid - 1] : 0);
    int base = g_bpre[b];
    if (i < NN) {
        g_offs[i + 1] = base + incl;
        g_cursor[i]   = base + incl - v;
    }
    if (i == 0) g_offs[0] = 0;
}

__global__ void k_scatter(const int* __restrict__ ei) {
    int e = blockIdx.x * blockDim.x + threadIdx.x;
    if (e < EE) {
        int d = ei[EE + e];
        int s = ei[e];
        if (d >= 0 && d < NN) {
            int pos = atomicAdd(&g_cursor[d], 1);
            if (pos >= 0 && pos < EE) g_csr[pos] = s;
        }
    }
}

// ---------------- embed: h = feature @ emb_w + emb_b (SIMT fp32) -------------
__global__ __launch_bounds__(256) void k_embed(const float* __restrict__ X,
                                               const float* __restrict__ W,
                                               const float* __restrict__ bias) {
    __shared__ float Ws[IN_DIM * HID];
    __shared__ float Xs[32 * IN_DIM];
    int t = threadIdx.x;
    int m0 = blockIdx.x * 32;
    for (int idx = t; idx < IN_DIM * HID; idx += 256) Ws[idx] = W[idx];
    for (int idx = t; idx < 32 * IN_DIM; idx += 256) {
        int m = m0 + (idx >> 7);
        Xs[idx] = (m < NN) ? X[m * IN_DIM + (idx & 127)] : 0.f;
    }
    __syncthreads();
    int tx = t & 31, ty = t >> 5;
    int c0 = tx * 2, r0 = ty * 4;
    float acc[4][2];
    #pragma unroll
    for (int i = 0; i < 4; i++) { acc[i][0] = 0.f; acc[i][1] = 0.f; }
    #pragma unroll 8
    for (int k = 0; k < IN_DIM; k++) {
        float2 w = *(const float2*)&Ws[k * HID + c0];
        #pragma unroll
        for (int i = 0; i < 4; i++) {
            float x = Xs[(r0 + i) * IN_DIM + k];
            acc[i][0] += x * w.x;
            acc[i][1] += x * w.y;
        }
    }
    float b0 = bias[c0], b1 = bias[c0 + 1];
    #pragma unroll
    for (int i = 0; i < 4; i++) {
        int m = m0 + r0 + i;
        if (m < NN) {
            g_h[m * HID + c0]     = acc[i][0] + b0;
            g_h[m * HID + c0 + 1] = acc[i][1] + b1;
        }
    }
}

// ---------------- layer linears + fused BN of previous layer -----------------
// If l > 0: X tile = g_h + relu(bn(g_hp)) using stats[l-1], written back to g_h.
__global__ __launch_bounds__(256) void k_abde(
    const float* __restrict__ Aw, const float* __restrict__ Bw,
    const float* __restrict__ Dw, const float* __restrict__ Ew,
    const float* __restrict__ Ab, const float* __restrict__ Bb,
    const float* __restrict__ Db, const float* __restrict__ Eb,
    const float* __restrict__ pg, const float* __restrict__ pb,  // prev gamma/beta
    int l) {
    __shared__ float Ws[HID * 128];
    __shared__ float Xs[64 * HID];
    int t = threadIdx.x;
    int m0 = blockIdx.x * 64;
    const float invN = 1.f / (float)NN;

    for (int idx = t; idx < 64 * (HID / 4); idx += 256) {
        int m = m0 + idx / (HID / 4);
        int c4 = (idx % (HID / 4)) * 4;
        float4 v = make_float4(0.f, 0.f, 0.f, 0.f);
        if (m < NN) {
            v = *(const float4*)&g_h[m * HID + c4];
            if (l > 0) {
                const float* st = g_stats[l - 1];
                float4 hp = *(const float4*)&g_hp[m * HID + c4];
                #pragma unroll
                for (int j = 0; j < 4; j++) {
                    int c = c4 + j;
                    float mu  = st[c] * invN;
                    float var = st[HID + c] * invN - mu * mu;
                    float hpv = (j == 0) ? hp.x : (j == 1) ? hp.y : (j == 2) ? hp.z : hp.w;
                    float xn  = (hpv - mu) * rsqrtf(var + 1e-5f);
                    float vv  = fmaxf(pg[c] * xn + pb[c], 0.f);
                    if (j == 0) v.x += vv; else if (j == 1) v.y += vv;
                    else if (j == 2) v.z += vv; else v.w += vv;
                }
                *(float4*)&g_h[m * HID + c4] = v;   // residual-applied h for next layer
            }
        }
        *(float4*)&Xs[idx * 4] = v;
    }

    const int tx = t & 31, ty = t >> 5;
    const int c0 = tx * 4, r0 = ty * 8;

    #pragma unroll
    for (int half = 0; half < 2; half++) {
        for (int idx = t; idx < HID * 128; idx += 256) {
            int k = idx >> 7, c = idx & 127;
            int gc = half * 128 + c;
            int sel = gc >> 6;
            const float* W = (sel == 0) ? Aw : (sel == 1) ? Bw : (sel == 2) ? Dw : Ew;
            Ws[idx] = W[k * HID + (gc & 63)];
        }
        __syncthreads();

        float acc[8][4];
        #pragma unroll
        for (int i = 0; i < 8; i++)
            #pragma unroll
            for (int j = 0; j < 4; j++) acc[i][j] = 0.f;

        #pragma unroll 4
        for (int k0 = 0; k0 < HID; k0 += 4) {
            float4 xv[8];
            #pragma unroll
            for (int i = 0; i < 8; i++)
                xv[i] = *(const float4*)&Xs[(r0 + i) * HID + k0];
            #pragma unroll
            for (int kk = 0; kk < 4; kk++) {
                float4 w = *(const float4*)&Ws[(k0 + kk) * 128 + c0];
                #pragma unroll
                for (int i = 0; i < 8; i++) {
                    float x = (kk == 0) ? xv[i].x : (kk == 1) ? xv[i].y
                            : (kk == 2) ? xv[i].z : xv[i].w;
                    acc[i][0] += x * w.x; acc[i][1] += x * w.y;
                    acc[i][2] += x * w.z; acc[i][3] += x * w.w;
                }
            }
        }

        int gc0 = half * 128 + c0;
        int sel = gc0 >> 6, cc = gc0 & 63;
        const float* bp = (sel == 0) ? Ab : (sel == 1) ? Bb : (sel == 2) ? Db : Eb;
        float b0 = bp[cc], b1 = bp[cc + 1], b2 = bp[cc + 2], b3 = bp[cc + 3];

        if (sel == 0 || sel == 3) {
            float* Y = (sel == 0) ? g_A : g_E;
            #pragma unroll
            for (int i = 0; i < 8; i++) {
                int m = m0 + r0 + i;
                if (m < NN) {
                    float4 v = make_float4(acc[i][0] + b0, acc[i][1] + b1,
                                           acc[i][2] + b2, acc[i][3] + b3);
                    *(float4*)&Y[m * HID + cc] = v;
                }
            }
        } else {
            int boff = (sel == 1) ? 1 : 0;
            #pragma unroll
            for (int i = 0; i < 8; i++) {
                int m = m0 + r0 + i;
                if (m < NN) {
                    int base = m * 64 + cc + boff;
                    g_BD[base]     = pack_bf16x2(acc[i][0] + b0, acc[i][1] + b1);
                    g_BD[base + 2] = pack_bf16x2(acc[i][2] + b2, acc[i][3] + b3);
                }
            }
        }
        __syncthreads();
    }
}

// ---------------- edge aggregation + fused BN stats (4-edge unrolled) ---------
__global__ __launch_bounds__(256) void k_agg(int l) {
    __shared__ float red_s[8][64], red_q[8][64];
    int w = threadIdx.x >> 5, lane = threadIdx.x & 31;
    int base = (blockIdx.x * 8 + w) * 4;
    float sx = 0.f, sy = 0.f, qx = 0.f, qy = 0.f;
    #pragma unroll 1
    for (int i = 0; i < 4; i++) {
        int gw = base + i;
        if (gw >= NN) break;
        int s0 = g_offs[gw], s1 = g_offs[gw + 1];
        int off = gw * HID + lane * 2;
        float2 el = *(const float2*)&g_E[off];
        float nx = 0.f, ny = 0.f, dx = 0.f, dy = 0.f;
        int k = s0;
        for (; k + 3 < s1; k += 4) {
            int sa = g_csr[k], sb = g_csr[k + 1], sc = g_csr[k + 2], sd = g_csr[k + 3];
            uint2 va = *(const uint2*)&g_BD[sa * 64 + lane * 2];
            uint2 vb = *(const uint2*)&g_BD[sb * 64 + lane * 2];
            uint2 vc = *(const uint2*)&g_BD[sc * 64 + lane * 2];
            uint2 vd = *(const uint2*)&g_BD[sd * 64 + lane * 2];
            float2 da = unpack_bf16x2(va.x), ba = unpack_bf16x2(va.y);
            float2 db = unpack_bf16x2(vb.x), bb = unpack_bf16x2(vb.y);
            float2 dc = unpack_bf16x2(vc.x), bc = unpack_bf16x2(vc.y);
            float2 dd = unpack_bf16x2(vd.x), bd = unpack_bf16x2(vd.y);
            float s0x = sigmoid_fast(da.x + el.x), s0y = sigmoid_fast(da.y + el.y);
            float s1x = sigmoid_fast(db.x + el.x), s1y = sigmoid_fast(db.y + el.y);
            float s2x = sigmoid_fast(dc.x + el.x), s2y = sigmoid_fast(dc.y + el.y);
            float s3x = sigmoid_fast(dd.x + el.x), s3y = sigmoid_fast(dd.y + el.y);
            nx += s0x * ba.x + s1x * bb.x + s2x * bc.x + s3x * bd.x;
            ny += s0y * ba.y + s1y * bb.y + s2y * bc.y + s3y * bd.y;
            dx += s0x + s1x + s2x + s3x;
            dy += s0y + s1y + s2y + s3y;
        }
        for (; k < s1; k++) {
            int sa = g_csr[k];
            uint2 va = *(const uint2*)&g_BD[sa * 64 + lane * 2];
            float2 da = unpack_bf16x2(va.x), ba = unpack_bf16x2(va.y);
            float ssx = sigmoid_fast(da.x + el.x);
            float ssy = sigmoid_fast(da.y + el.y);
            nx += ssx * ba.x; ny += ssy * ba.y;
            dx += ssx;        dy += ssy;
        }
        float2 aa = *(const float2*)&g_A[off];
        float ox = aa.x + nx / (dx + 1e-6f);
        float oy = aa.y + ny / (dy + 1e-6f);
        *(float2*)&g_hp[off] = make_float2(ox, oy);
        sx += ox; sy += oy; qx += ox * ox; qy += oy * oy;
    }
    red_s[w][lane * 2] = sx;  red_s[w][lane * 2 + 1] = sy;
    red_q[w][lane * 2] = qx;  red_q[w][lane * 2 + 1] = qy;
    __syncthreads();
    int t = threadIdx.x;
    if (t < 64) {
        float s = 0.f, q = 0.f;
        #pragma unroll
        for (int ww = 0; ww < 8; ww++) { s += red_s[ww][t]; q += red_q[ww][t]; }
        atomicAdd(&g_stats[l][t], s);
        atomicAdd(&g_stats[l][HID + t], q);
    }
}

// ---------------- final BN/ReLU/residual -> d_out -----------------------------
__global__ __launch_bounds__(256) void k_bn_final(const float* __restrict__ gamma,
                                                  const float* __restrict__ beta,
                                                  float* __restrict__ out) {
    int idx = blockIdx.x * blockDim.x + threadIdx.x;
    if (idx >= NN * HID) return;
    int c = idx & 63;
    const float* st = g_stats[NL - 1];
    const float invN = 1.f / (float)NN;
    float mu  = st[c] * invN;
    float var = st[HID + c] * invN - mu * mu;
    float xn = (g_hp[idx] - mu) * rsqrtf(var + 1e-5f);
    float v = fmaxf(gamma[c] * xn + beta[c], 0.f);
    out[idx] = g_h[idx] + v;
}

// ---------------- launch ------------------------------------------------------
extern "C" void kernel_launch(void* const* d_in, const int* in_sizes, int n_in,
                              void* d_out, int out_size) {
    const float* feature = (const float*)d_in[0];
    const int*   ei      = (const int*)d_in[1];     // int32 (JAX x64 disabled)
    const float* emb_w   = (const float*)d_in[2];
    const float* emb_b   = (const float*)d_in[3];
    const float* Aw      = (const float*)d_in[4];
    const float* Ab      = (const float*)d_in[5];
    const float* Bw      = (const float*)d_in[6];
    const float* Bb      = (const float*)d_in[7];
    const float* Dw      = (const float*)d_in[8];
    const float* Db      = (const float*)d_in[9];
    const float* Ew      = (const float*)d_in[10];
    const float* Eb      = (const float*)d_in[11];
    const float* gamma   = (const float*)d_in[12];
    const float* beta    = (const float*)d_in[13];
    float* out = (float*)d_out;

    k_clear_deg<<<(NN + 255) / 256, 256>>>();
    k_hist<<<(EE + 255) / 256, 256>>>(ei);
    k_bsum<<<SCAN_B, 256>>>();
    k_bscan<<<1, 256>>>();
    k_offs<<<SCAN_B, 256>>>();
    k_scatter<<<(EE + 255) / 256, 256>>>(ei);

    k_embed<<<(NN + 31) / 32, 256>>>(feature, emb_w, emb_b);

    for (int l = 0; l < NL; l++) {
        const float* pg = (l > 0) ? gamma + (l - 1) * HID : gamma;
        const float* pb = (l > 0) ? beta  + (l - 1) * HID : beta;
        k_abde<<<(NN + 63) / 64, 256>>>(
            Aw + l * HID * HID, Bw + l * HID * HID,
            Dw + l * HID * HID, Ew + l * HID * HID,
            Ab + l * HID, Bb + l * HID, Db + l * HID, Eb + l * HID,
            pg, pb, l);
        k_agg<<<(NN + 31) / 32, 256>>>(l);
    }
    k_bn_final<<<(NN * HID + 255) / 256, 256>>>(gamma + (NL - 1) * HID,
                                                beta + (NL - 1) * HID, out);
}

// round 9
// speedup vs baseline: 1.5857x; 1.1459x over previous
#include <cuda_runtime.h>
#include <cuda_bf16.h>

#define NN 50000
#define EE 1000000
#define IN_DIM 128
#define HID 64
#define NL 4
#define SCAN_B 196   // ceil(NN/256)

// ---------------- scratch (static device globals; no allocation) -------------
__device__ float    g_h[NN * HID];     // node features (residual-applied)
__device__ float    g_hp[NN * HID];    // pre-BN layer output
__device__ float    g_A[NN * HID];
__device__ float    g_E[NN * HID];
__device__ unsigned g_BD[NN * 64];     // interleaved: even word = D pack, odd = B pack
__device__ int      g_deg[NN];
__device__ int      g_offs[NN + 1];
__device__ int      g_cursor[NN];
__device__ int      g_csr[EE];
__device__ float    g_stats[NL][2 * HID];  // per-layer: sum, sumsq
__device__ int      g_bsum[256];
__device__ int      g_bpre[256];

__device__ __forceinline__ unsigned pack_bf16x2(float a, float b) {
    __nv_bfloat162 h = __floats2bfloat162_rn(a, b);
    return *reinterpret_cast<unsigned*>(&h);
}
__device__ __forceinline__ float2 unpack_bf16x2(unsigned u) {
    __nv_bfloat162 h = *reinterpret_cast<__nv_bfloat162*>(&u);
    return __bfloat1622float2(h);
}
__device__ __forceinline__ float sigmoid_fast(float x) {
    float t;
    asm("tanh.approx.f32 %0, %1;" : "=f"(t) : "f"(0.5f * x));
    return fmaf(t, 0.5f, 0.5f);
}
// split consecutive-k pair (x0 even k low half) into bf16 hi-word and lo-word
__device__ __forceinline__ void split_pair(float x0, float x1,
                                           unsigned& hw, unsigned& lw) {
    __nv_bfloat16 h0 = __float2bfloat16(x0);
    __nv_bfloat16 h1 = __float2bfloat16(x1);
    float r0 = x0 - __bfloat162float(h0);
    float r1 = x1 - __bfloat162float(h1);
    __nv_bfloat16 l0 = __float2bfloat16(r0);
    __nv_bfloat16 l1 = __float2bfloat16(r1);
    hw = (unsigned)__bfloat16_as_ushort(h0) | ((unsigned)__bfloat16_as_ushort(h1) << 16);
    lw = (unsigned)__bfloat16_as_ushort(l0) | ((unsigned)__bfloat16_as_ushort(l1) << 16);
}
__device__ __forceinline__ void mma_bf16(float* d, const unsigned* a, const unsigned* b) {
    asm("mma.sync.aligned.m16n8k16.row.col.f32.bf16.bf16.f32 "
        "{%0,%1,%2,%3}, {%4,%5,%6,%7}, {%8,%9}, {%0,%1,%2,%3};"
        : "+f"(d[0]), "+f"(d[1]), "+f"(d[2]), "+f"(d[3])
        : "r"(a[0]), "r"(a[1]), "r"(a[2]), "r"(a[3]), "r"(b[0]), "r"(b[1]));
}

// ---------------- CSR build ----------------------------------------------------
__global__ void k_clear_deg() {
    int i = blockIdx.x * blockDim.x + threadIdx.x;
    if (i < NN) g_deg[i] = 0;
    if (i < NL * 2 * HID) ((float*)g_stats)[i] = 0.f;
}

__global__ void k_hist(const int* __restrict__ ei) {
    int e = blockIdx.x * blockDim.x + threadIdx.x;
    if (e < EE) {
        int d = ei[EE + e];
        if (d >= 0 && d < NN) atomicAdd(&g_deg[d], 1);
    }
}

__global__ void k_bsum() {
    __shared__ int ws[8];
    int t = threadIdx.x, b = blockIdx.x;
    int i = b * 256 + t;
    int v = (i < NN) ? g_deg[i] : 0;
    #pragma unroll
    for (int o = 16; o; o >>= 1) v += __shfl_down_sync(0xffffffffu, v, o);
    if ((t & 31) == 0) ws[t >> 5] = v;
    __syncthreads();
    if (t == 0) {
        int s = 0;
        #pragma unroll
        for (int j = 0; j < 8; j++) s += ws[j];
        g_bsum[b] = s;
    }
}

__global__ void k_bscan() {
    __shared__ int ws[8];
    int t = threadIdx.x;
    int v = (t < SCAN_B) ? g_bsum[t] : 0;
    int lane = t & 31, wid = t >> 5;
    int x = v;
    #pragma unroll
    for (int o = 1; o < 32; o <<= 1) {
        int y = __shfl_up_sync(0xffffffffu, x, o);
        if (lane >= o) x += y;
    }
    if (lane == 31) ws[wid] = x;
    __syncthreads();
    if (t < 8) {
        int w = ws[t];
        #pragma unroll
        for (int o = 1; o < 8; o <<= 1) {
            int y = __shfl_up_sync(0xffu, w, o);
            if (t >= o) w += y;
        }
        ws[t] = w;
    }
    __syncthreads();
    int incl = x + (wid ? ws[wid - 1] : 0);
    g_bpre[t] = incl - v;
}

__global__ void k_offs() {
    __shared__ int ws[8];
    int t = threadIdx.x, b = blockIdx.x;
    int i = b * 256 + t;
    int v = (i < NN) ? g_deg[i] : 0;
    int lane = t & 31, wid = t >> 5;
    int x = v;
    #pragma unroll
    for (int o = 1; o < 32; o <<= 1) {
        int y = __shfl_up_sync(0xffffffffu, x, o);
        if (lane >= o) x += y;
    }
    if (lane == 31) ws[wid] = x;
    __syncthreads();
    if (t < 8) {
        int w = ws[t];
        #pragma unroll
        for (int o = 1; o < 8; o <<= 1) {
            int y = __shfl_up_sync(0xffu, w, o);
            if (t >= o) w += y;
        }
        ws[t] = w;
    }
    __syncthreads();
    int incl = x + (wid ? ws[wid - 1] : 0);
    int base = g_bpre[b];
    if (i < NN) {
        g_offs[i + 1] = base + incl;
        g_cursor[i]   = base + incl - v;
    }
    if (i == 0) g_offs[0] = 0;
}

__global__ void k_scatter(const int* __restrict__ ei) {
    int e = blockIdx.x * blockDim.x + threadIdx.x;
    if (e < EE) {
        int d = ei[EE + e];
        int s = ei[e];
        if (d >= 0 && d < NN) {
            int pos = atomicAdd(&g_cursor[d], 1);
            if (pos >= 0 && pos < EE) g_csr[pos] = s;
        }
    }
}

// ---------------- embed: h = feature @ emb_w + emb_b (SIMT fp32) -------------
__global__ __launch_bounds__(256) void k_embed(const float* __restrict__ X,
                                               const float* __restrict__ W,
                                               const float* __restrict__ bias) {
    __shared__ float Ws[IN_DIM * HID];
    __shared__ float Xs[32 * IN_DIM];
    int t = threadIdx.x;
    int m0 = blockIdx.x * 32;
    for (int idx = t; idx < IN_DIM * HID; idx += 256) Ws[idx] = W[idx];
    for (int idx = t; idx < 32 * IN_DIM; idx += 256) {
        int m = m0 + (idx >> 7);
        Xs[idx] = (m < NN) ? X[m * IN_DIM + (idx & 127)] : 0.f;
    }
    __syncthreads();
    int tx = t & 31, ty = t >> 5;
    int c0 = tx * 2, r0 = ty * 4;
    float acc[4][2];
    #pragma unroll
    for (int i = 0; i < 4; i++) { acc[i][0] = 0.f; acc[i][1] = 0.f; }
    #pragma unroll 8
    for (int k = 0; k < IN_DIM; k++) {
        float2 w = *(const float2*)&Ws[k * HID + c0];
        #pragma unroll
        for (int i = 0; i < 4; i++) {
            float x = Xs[(r0 + i) * IN_DIM + k];
            acc[i][0] += x * w.x;
            acc[i][1] += x * w.y;
        }
    }
    float b0 = bias[c0], b1 = bias[c0 + 1];
    #pragma unroll
    for (int i = 0; i < 4; i++) {
        int m = m0 + r0 + i;
        if (m < NN) {
            g_h[m * HID + c0]     = acc[i][0] + b0;
            g_h[m * HID + c0 + 1] = acc[i][1] + b1;
        }
    }
}

// ---------------- layer linears: bf16 m16n8k16 MMA, 3-term compensation ------
// + fused BN/ReLU/residual of previous layer in X staging (writes g_h back).
// smem: Xh/Xl (64x32 words, 8KB each) + Wh/Wl (128x32 words, 16KB each) = 48KB.
// X swizzle: word (r,kp) at r*32 + (kp ^ ((r&7)<<2)); W: c*32 + (kp ^ ((c&7)<<2)).
__global__ __launch_bounds__(256) void k_abde(
    const float* __restrict__ Aw, const float* __restrict__ Bw,
    const float* __restrict__ Dw, const float* __restrict__ Ew,
    const float* __restrict__ Ab, const float* __restrict__ Bb,
    const float* __restrict__ Db, const float* __restrict__ Eb,
    const float* __restrict__ pg, const float* __restrict__ pb,
    int l) {
    __shared__ unsigned Xh[64 * 32], Xl[64 * 32];
    __shared__ unsigned Wh[128 * 32], Wl[128 * 32];
    int t = threadIdx.x;
    int m0 = blockIdx.x * 64;
    const float invN = 1.f / (float)NN;

    // ---- stage X: fused BN of prev layer, then bf16 hi/lo split -------------
    for (int idx = t; idx < 64 * 16; idx += 256) {
        int r = idx >> 4, c4 = (idx & 15) * 4;
        int m = m0 + r;
        float4 v = make_float4(0.f, 0.f, 0.f, 0.f);
        if (m < NN) {
            v = *(const float4*)&g_h[m * HID + c4];
            if (l > 0) {
                const float* st = g_stats[l - 1];
                float4 hp = *(const float4*)&g_hp[m * HID + c4];
                #pragma unroll
                for (int j = 0; j < 4; j++) {
                    int c = c4 + j;
                    float mu  = st[c] * invN;
                    float var = st[HID + c] * invN - mu * mu;
                    float hpv = (j == 0) ? hp.x : (j == 1) ? hp.y : (j == 2) ? hp.z : hp.w;
                    float xn  = (hpv - mu) * rsqrtf(var + 1e-5f);
                    float vv  = fmaxf(pg[c] * xn + pb[c], 0.f);
                    if (j == 0) v.x += vv; else if (j == 1) v.y += vv;
                    else if (j == 2) v.z += vv; else v.w += vv;
                }
                *(float4*)&g_h[m * HID + c4] = v;
            }
        }
        int kp0 = c4 >> 1;         // pair indices kp0, kp0+1
        unsigned hw, lw;
        int swz = (r & 7) << 2;
        split_pair(v.x, v.y, hw, lw);
        Xh[r * 32 + (kp0 ^ swz)] = hw;
        Xl[r * 32 + (kp0 ^ swz)] = lw;
        split_pair(v.z, v.w, hw, lw);
        Xh[r * 32 + ((kp0 + 1) ^ swz)] = hw;
        Xl[r * 32 + ((kp0 + 1) ^ swz)] = lw;
    }

    int lane = t & 31, w = t >> 5;
    int g = lane >> 2, tig = lane & 3;
    int mt = w & 3, ns = w >> 2;            // ns in {0,1}: 64-col strip in half
    int r0 = mt * 16 + g, r1 = r0 + 8;

    #pragma unroll
    for (int half = 0; half < 2; half++) {
        // ---- stage W half: cols [half*128, +128) of A|B|D|E concat ----------
        for (int idx = t; idx < 32 * 128; idx += 256) {
            int kp = idx >> 7, c = idx & 127;   // lanes: consecutive c -> coalesced
            int gc = half * 128 + c;
            int sel = gc >> 6, cc = gc & 63;
            const float* W = (sel == 0) ? Aw : (sel == 1) ? Bw : (sel == 2) ? Dw : Ew;
            float w0 = W[(2 * kp) * HID + cc];
            float w1 = W[(2 * kp + 1) * HID + cc];
            unsigned hw, lw;
            split_pair(w0, w1, hw, lw);
            int s = c * 32 + (kp ^ ((c & 7) << 2));
            Wh[s] = hw;
            Wl[s] = lw;
        }
        __syncthreads();

        float acc[8][4];
        #pragma unroll
        for (int i = 0; i < 8; i++)
            #pragma unroll
            for (int j = 0; j < 4; j++) acc[i][j] = 0.f;

        int swa0 = (r0 & 7) << 2, swa1 = (r1 & 7) << 2;
        #pragma unroll
        for (int ks = 0; ks < 4; ks++) {
            int kb = ks * 8;
            int kpa = kb + tig, kpb = kb + tig + 4;
            unsigned ah[4], al[4];
            int s0 = r0 * 32 + (kpa ^ swa0), s1 = r1 * 32 + (kpa ^ swa1);
            int s2 = r0 * 32 + (kpb ^ swa0), s3 = r1 * 32 + (kpb ^ swa1);
            ah[0] = Xh[s0]; ah[1] = Xh[s1]; ah[2] = Xh[s2]; ah[3] = Xh[s3];
            al[0] = Xl[s0]; al[1] = Xl[s1]; al[2] = Xl[s2]; al[3] = Xl[s3];
            #pragma unroll
            for (int nt = 0; nt < 8; nt++) {
                int c = ns * 64 + nt * 8 + g;
                int swc = (c & 7) << 2;
                int sb0 = c * 32 + (kpa ^ swc);
                int sb1 = c * 32 + (kpb ^ swc);
                unsigned bh[2] = {Wh[sb0], Wh[sb1]};
                unsigned bl[2] = {Wl[sb0], Wl[sb1]};
                mma_bf16(acc[nt], ah, bh);
                mma_bf16(acc[nt], al, bh);
                mma_bf16(acc[nt], ah, bl);
            }
        }

        // ---- store: warp's 64-col strip = one matrix (sel = half*2 + ns) ----
        int sel = half * 2 + ns;
        const float* bp = (sel == 0) ? Ab : (sel == 1) ? Bb : (sel == 2) ? Db : Eb;
        int mra = m0 + mt * 16 + g, mrb = mra + 8;
        if (sel == 0 || sel == 3) {
            float* Y = (sel == 0) ? g_A : g_E;
            #pragma unroll
            for (int nt = 0; nt < 8; nt++) {
                int cc = nt * 8 + 2 * tig;
                float b0v = bp[cc], b1v = bp[cc + 1];
                if (mra < NN)
                    *(float2*)&Y[mra * HID + cc] = make_float2(acc[nt][0] + b0v, acc[nt][1] + b1v);
                if (mrb < NN)
                    *(float2*)&Y[mrb * HID + cc] = make_float2(acc[nt][2] + b0v, acc[nt][3] + b1v);
            }
        } else {
            int boff = (sel == 1) ? 1 : 0;
            #pragma unroll
            for (int nt = 0; nt < 8; nt++) {
                int cc = nt * 8 + 2 * tig;
                float b0v = bp[cc], b1v = bp[cc + 1];
                if (mra < NN)
                    g_BD[mra * 64 + cc + boff] = pack_bf16x2(acc[nt][0] + b0v, acc[nt][1] + b1v);
                if (mrb < NN)
                    g_BD[mrb * 64 + cc + boff] = pack_bf16x2(acc[nt][2] + b0v, acc[nt][3] + b1v);
            }
        }
        __syncthreads();   // before next half overwrites Wh/Wl
    }
}

// ---------------- edge aggregation + fused BN stats (4-edge unrolled) ---------
__global__ __launch_bounds__(256) void k_agg(int l) {
    __shared__ float red_s[8][64], red_q[8][64];
    int w = threadIdx.x >> 5, lane = threadIdx.x & 31;
    int base = (blockIdx.x * 8 + w) * 4;
    float sx = 0.f, sy = 0.f, qx = 0.f, qy = 0.f;
    #pragma unroll 1
    for (int i = 0; i < 4; i++) {
        int gw = base + i;
        if (gw >= NN) break;
        int s0 = g_offs[gw], s1 = g_offs[gw + 1];
        int off = gw * HID + lane * 2;
        float2 el = *(const float2*)&g_E[off];
        float nx = 0.f, ny = 0.f, dx = 0.f, dy = 0.f;
        int k = s0;
        for (; k + 3 < s1; k += 4) {
            int sa = g_csr[k], sb = g_csr[k + 1], sc = g_csr[k + 2], sd = g_csr[k + 3];
            uint2 va = *(const uint2*)&g_BD[sa * 64 + lane * 2];
            uint2 vb = *(const uint2*)&g_BD[sb * 64 + lane * 2];
            uint2 vc = *(const uint2*)&g_BD[sc * 64 + lane * 2];
            uint2 vd = *(const uint2*)&g_BD[sd * 64 + lane * 2];
            float2 da = unpack_bf16x2(va.x), ba = unpack_bf16x2(va.y);
            float2 db = unpack_bf16x2(vb.x), bb = unpack_bf16x2(vb.y);
            float2 dc = unpack_bf16x2(vc.x), bc = unpack_bf16x2(vc.y);
            float2 dd = unpack_bf16x2(vd.x), bd = unpack_bf16x2(vd.y);
            float s0x = sigmoid_fast(da.x + el.x), s0y = sigmoid_fast(da.y + el.y);
            float s1x = sigmoid_fast(db.x + el.x), s1y = sigmoid_fast(db.y + el.y);
            float s2x = sigmoid_fast(dc.x + el.x), s2y = sigmoid_fast(dc.y + el.y);
            float s3x = sigmoid_fast(dd.x + el.x), s3y = sigmoid_fast(dd.y + el.y);
            nx += s0x * ba.x + s1x * bb.x + s2x * bc.x + s3x * bd.x;
            ny += s0y * ba.y + s1y * bb.y + s2y * bc.y + s3y * bd.y;
            dx += s0x + s1x + s2x + s3x;
            dy += s0y + s1y + s2y + s3y;
        }
        for (; k < s1; k++) {
            int sa = g_csr[k];
            uint2 va = *(const uint2*)&g_BD[sa * 64 + lane * 2];
            float2 da = unpack_bf16x2(va.x), ba = unpack_bf16x2(va.y);
            float ssx = sigmoid_fast(da.x + el.x);
            float ssy = sigmoid_fast(da.y + el.y);
            nx += ssx * ba.x; ny += ssy * ba.y;
            dx += ssx;        dy += ssy;
        }
        float2 aa = *(const float2*)&g_A[off];
        float ox = aa.x + nx / (dx + 1e-6f);
        float oy = aa.y + ny / (dy + 1e-6f);
        *(float2*)&g_hp[off] = make_float2(ox, oy);
        sx += ox; sy += oy; qx += ox * ox; qy += oy * oy;
    }
    red_s[w][lane * 2] = sx;  red_s[w][lane * 2 + 1] = sy;
    red_q[w][lane * 2] = qx;  red_q[w][lane * 2 + 1] = qy;
    __syncthreads();
    int t = threadIdx.x;
    if (t < 64) {
        float s = 0.f, q = 0.f;
        #pragma unroll
        for (int ww = 0; ww < 8; ww++) { s += red_s[ww][t]; q += red_q[ww][t]; }
        atomicAdd(&g_stats[l][t], s);
        atomicAdd(&g_stats[l][HID + t], q);
    }
}

// ---------------- final BN/ReLU/residual -> d_out -----------------------------
__global__ __launch_bounds__(256) void k_bn_final(const float* __restrict__ gamma,
                                                  const float* __restrict__ beta,
                                                  float* __restrict__ out) {
    int idx = blockIdx.x * blockDim.x + threadIdx.x;
    if (idx >= NN * HID) return;
    int c = idx & 63;
    const float* st = g_stats[NL - 1];
    const float invN = 1.f / (float)NN;
    float mu  = st[c] * invN;
    float var = st[HID + c] * invN - mu * mu;
    float xn = (g_hp[idx] - mu) * rsqrtf(var + 1e-5f);
    float v = fmaxf(gamma[c] * xn + beta[c], 0.f);
    out[idx] = g_h[idx] + v;
}

// ---------------- launch ------------------------------------------------------
extern "C" void kernel_launch(void* const* d_in, const int* in_sizes, int n_in,
                              void* d_out, int out_size) {
    const float* feature = (const float*)d_in[0];
    const int*   ei      = (const int*)d_in[1];     // int32 (JAX x64 disabled)
    const float* emb_w   = (const float*)d_in[2];
    const float* emb_b   = (const float*)d_in[3];
    const float* Aw      = (const float*)d_in[4];
    const float* Ab      = (const float*)d_in[5];
    const float* Bw      = (const float*)d_in[6];
    const float* Bb      = (const float*)d_in[7];
    const float* Dw      = (const float*)d_in[8];
    const float* Db      = (const float*)d_in[9];
    const float* Ew      = (const float*)d_in[10];
    const float* Eb      = (const float*)d_in[11];
    const float* gamma   = (const float*)d_in[12];
    const float* beta    = (const float*)d_in[13];
    float* out = (float*)d_out;

    k_clear_deg<<<(NN + 255) / 256, 256>>>();
    k_hist<<<(EE + 255) / 256, 256>>>(ei);
    k_bsum<<<SCAN_B, 256>>>();
    k_bscan<<<1, 256>>>();
    k_offs<<<SCAN_B, 256>>>();
    k_scatter<<<(EE + 255) / 256, 256>>>(ei);

    k_embed<<<(NN + 31) / 32, 256>>>(feature, emb_w, emb_b);

    for (int l = 0; l < NL; l++) {
        const float* pg = (l > 0) ? gamma + (l - 1) * HID : gamma;
        const float* pb = (l > 0) ? beta  + (l - 1) * HID : beta;
        k_abde<<<(NN + 63) / 64, 256>>>(
            Aw + l * HID * HID, Bw + l * HID * HID,
            Dw + l * HID * HID, Ew + l * HID * HID,
            Ab + l * HID, Bb + l * HID, Db + l * HID, Eb + l * HID,
            pg, pb, l);
        k_agg<<<(NN + 31) / 32, 256>>>(l);
    }
    k_bn_final<<<(NN * HID + 255) / 256, 256>>>(gamma + (NL - 1) * HID,
                                                beta + (NL - 1) * HID, out);
}

// round 10
// speedup vs baseline: 1.7152x; 1.0817x over previous
#include <cuda_runtime.h>
#include <cuda_bf16.h>

#define NN 50000
#define EE 1000000
#define IN_DIM 128
#define HID 64
#define NL 4
#define SCAN_B 196   // ceil(NN/256)

// ---------------- scratch (static device globals; no allocation) -------------
__device__ float    g_h[NN * HID];     // node features (residual-applied)
__device__ float    g_hp[NN * HID];    // pre-BN layer output
__device__ float    g_A[NN * HID];
__device__ float    g_E[NN * HID];
__device__ unsigned g_BD[NN * 64];     // interleaved: even word = D pack, odd = B pack
__device__ int      g_deg[NN];
__device__ int      g_offs[NN + 1];
__device__ int      g_cursor[NN];
__device__ int      g_csr[EE];
__device__ float    g_stats[NL][2 * HID];  // per-layer: sum, sumsq
__device__ int      g_bpre[256];

__device__ __forceinline__ unsigned pack_bf16x2(float a, float b) {
    __nv_bfloat162 h = __floats2bfloat162_rn(a, b);
    return *reinterpret_cast<unsigned*>(&h);
}
__device__ __forceinline__ float2 unpack_bf16x2(unsigned u) {
    __nv_bfloat162 h = *reinterpret_cast<__nv_bfloat162*>(&u);
    return __bfloat1622float2(h);
}
__device__ __forceinline__ float sigmoid_fast(float x) {
    float t;
    asm("tanh.approx.f32 %0, %1;" : "=f"(t) : "f"(0.5f * x));
    return fmaf(t, 0.5f, 0.5f);
}
// split consecutive-k pair into bf16 hi-word and lo-word
__device__ __forceinline__ void split_pair(float x0, float x1,
                                           unsigned& hw, unsigned& lw) {
    __nv_bfloat16 h0 = __float2bfloat16(x0);
    __nv_bfloat16 h1 = __float2bfloat16(x1);
    float r0 = x0 - __bfloat162float(h0);
    float r1 = x1 - __bfloat162float(h1);
    __nv_bfloat16 l0 = __float2bfloat16(r0);
    __nv_bfloat16 l1 = __float2bfloat16(r1);
    hw = (unsigned)__bfloat16_as_ushort(h0) | ((unsigned)__bfloat16_as_ushort(h1) << 16);
    lw = (unsigned)__bfloat16_as_ushort(l0) | ((unsigned)__bfloat16_as_ushort(l1) << 16);
}
__device__ __forceinline__ void mma_bf16(float* d, const unsigned* a, const unsigned* b) {
    asm("mma.sync.aligned.m16n8k16.row.col.f32.bf16.bf16.f32 "
        "{%0,%1,%2,%3}, {%4,%5,%6,%7}, {%8,%9}, {%0,%1,%2,%3};"
        : "+f"(d[0]), "+f"(d[1]), "+f"(d[2]), "+f"(d[3])
        : "r"(a[0]), "r"(a[1]), "r"(a[2]), "r"(a[3]), "r"(b[0]), "r"(b[1]));
}

// ---------------- CSR build ----------------------------------------------------
__global__ void k_clear_deg() {
    int i = blockIdx.x * blockDim.x + threadIdx.x;
    if (i < NN) g_deg[i] = 0;
    if (i < NL * 2 * HID) ((float*)g_stats)[i] = 0.f;
}

__global__ void k_hist(const int* __restrict__ ei) {
    int e = (blockIdx.x * blockDim.x + threadIdx.x) * 2;
    if (e < EE) {
        int2 d2 = *(const int2*)&ei[EE + e];
        if (d2.x >= 0 && d2.x < NN) atomicAdd(&g_deg[d2.x], 1);
        if (d2.y >= 0 && d2.y < NN) atomicAdd(&g_deg[d2.y], 1);
    }
}

// merged: per-chunk sums (256 nodes each) + exclusive scan, single block
__global__ void k_scan1() {
    __shared__ int sums[224];
    __shared__ int ws[8];
    int t = threadIdx.x, lane = t & 31, w = t >> 5;
    for (int c = t; c < 224; c += 256) sums[c] = 0;
    __syncthreads();
    for (int c = w; c < SCAN_B; c += 8) {
        int s = 0;
        #pragma unroll
        for (int i = 0; i < 8; i++) {
            int idx = c * 256 + i * 32 + lane;
            s += (idx < NN) ? g_deg[idx] : 0;
        }
        #pragma unroll
        for (int o = 16; o; o >>= 1) s += __shfl_down_sync(0xffffffffu, s, o);
        if (lane == 0) sums[c] = s;
    }
    __syncthreads();
    int v = (t < SCAN_B) ? sums[t] : 0;
    int x = v;
    #pragma unroll
    for (int o = 1; o < 32; o <<= 1) {
        int y = __shfl_up_sync(0xffffffffu, x, o);
        if (lane >= o) x += y;
    }
    if (lane == 31) ws[w] = x;
    __syncthreads();
    if (t < 8) {
        int q = ws[t];
        #pragma unroll
        for (int o = 1; o < 8; o <<= 1) {
            int y = __shfl_up_sync(0xffu, q, o);
            if (t >= o) q += y;
        }
        ws[t] = q;
    }
    __syncthreads();
    int incl = x + (w ? ws[w - 1] : 0);
    g_bpre[t] = incl - v;
}

__global__ void k_offs() {
    __shared__ int ws[8];
    int t = threadIdx.x, b = blockIdx.x;
    int i = b * 256 + t;
    int v = (i < NN) ? g_deg[i] : 0;
    int lane = t & 31, wid = t >> 5;
    int x = v;
    #pragma unroll
    for (int o = 1; o < 32; o <<= 1) {
        int y = __shfl_up_sync(0xffffffffu, x, o);
        if (lane >= o) x += y;
    }
    if (lane == 31) ws[wid] = x;
    __syncthreads();
    if (t < 8) {
        int w = ws[t];
        #pragma unroll
        for (int o = 1; o < 8; o <<= 1) {
            int y = __shfl_up_sync(0xffu, w, o);
            if (t >= o) w += y;
        }
        ws[t] = w;
    }
    __syncthreads();
    int incl = x + (wid ? ws[wid - 1] : 0);
    int base = g_bpre[b];
    if (i < NN) {
        g_offs[i + 1] = base + incl;
        g_cursor[i]   = base + incl - v;
    }
    if (i == 0) g_offs[0] = 0;
}

__global__ void k_scatter(const int* __restrict__ ei) {
    int e = (blockIdx.x * blockDim.x + threadIdx.x) * 2;
    if (e < EE) {
        int2 s2 = *(const int2*)&ei[e];
        int2 d2 = *(const int2*)&ei[EE + e];
        if (d2.x >= 0 && d2.x < NN) {
            int pos = atomicAdd(&g_cursor[d2.x], 1);
            if (pos >= 0 && pos < EE) g_csr[pos] = s2.x;
        }
        if (d2.y >= 0 && d2.y < NN) {
            int pos = atomicAdd(&g_cursor[d2.y], 1);
            if (pos >= 0 && pos < EE) g_csr[pos] = s2.y;
        }
    }
}

// ---------------- embed: bf16 MMA 3-term, 64 rows x 64 cols, K=128 -----------
__global__ __launch_bounds__(256) void k_embed(const float* __restrict__ X,
                                               const float* __restrict__ W,
                                               const float* __restrict__ bias) {
    __shared__ unsigned Xh[64 * 32], Xl[64 * 32];
    __shared__ unsigned Wh[64 * 32], Wl[64 * 32];
    int t = threadIdx.x;
    int m0 = blockIdx.x * 64;
    int lane = t & 31, w = t >> 5;
    int g = lane >> 2, tig = lane & 3;
    int mt = w & 3, ns = w >> 2;
    int r0 = mt * 16 + g, r1 = r0 + 8;

    float acc[4][4];
    #pragma unroll
    for (int i = 0; i < 4; i++)
        #pragma unroll
        for (int j = 0; j < 4; j++) acc[i][j] = 0.f;

    #pragma unroll
    for (int kc = 0; kc < 2; kc++) {
        // stage X chunk: rows 0..63, k in [kc*64, +64)
        for (int idx = t; idx < 64 * 16; idx += 256) {
            int r = idx >> 4, c4 = (idx & 15) * 4;
            int m = m0 + r;
            float4 v = make_float4(0.f, 0.f, 0.f, 0.f);
            if (m < NN) v = *(const float4*)&X[m * IN_DIM + kc * 64 + c4];
            int kp0 = c4 >> 1, swz = (r & 7) << 2;
            unsigned hw, lw;
            split_pair(v.x, v.y, hw, lw);
            Xh[r * 32 + (kp0 ^ swz)] = hw;
            Xl[r * 32 + (kp0 ^ swz)] = lw;
            split_pair(v.z, v.w, hw, lw);
            Xh[r * 32 + ((kp0 + 1) ^ swz)] = hw;
            Xl[r * 32 + ((kp0 + 1) ^ swz)] = lw;
        }
        // stage W chunk: k in [kc*64, +64), all 64 cols
        for (int idx = t; idx < 32 * 64; idx += 256) {
            int kp = idx >> 6, c = idx & 63;
            float w0 = W[(kc * 64 + 2 * kp) * HID + c];
            float w1 = W[(kc * 64 + 2 * kp + 1) * HID + c];
            unsigned hw, lw;
            split_pair(w0, w1, hw, lw);
            int s = c * 32 + (kp ^ ((c & 7) << 2));
            Wh[s] = hw;
            Wl[s] = lw;
        }
        __syncthreads();

        int swa0 = (r0 & 7) << 2, swa1 = (r1 & 7) << 2;
        #pragma unroll
        for (int ks = 0; ks < 4; ks++) {
            int kpa = ks * 8 + tig, kpb = kpa + 4;
            unsigned ah[4], al[4];
            int s0 = r0 * 32 + (kpa ^ swa0), s1 = r1 * 32 + (kpa ^ swa1);
            int s2 = r0 * 32 + (kpb ^ swa0), s3 = r1 * 32 + (kpb ^ swa1);
            ah[0] = Xh[s0]; ah[1] = Xh[s1]; ah[2] = Xh[s2]; ah[3] = Xh[s3];
            al[0] = Xl[s0]; al[1] = Xl[s1]; al[2] = Xl[s2]; al[3] = Xl[s3];
            #pragma unroll
            for (int nt = 0; nt < 4; nt++) {
                int c = ns * 32 + nt * 8 + g;
                int swc = (c & 7) << 2;
                int sb0 = c * 32 + (kpa ^ swc);
                int sb1 = c * 32 + (kpb ^ swc);
                unsigned bh[2] = {Wh[sb0], Wh[sb1]};
                unsigned bl[2] = {Wl[sb0], Wl[sb1]};
                mma_bf16(acc[nt], ah, bh);
                mma_bf16(acc[nt], al, bh);
                mma_bf16(acc[nt], ah, bl);
            }
        }
        __syncthreads();
    }

    int mra = m0 + mt * 16 + g, mrb = mra + 8;
    #pragma unroll
    for (int nt = 0; nt < 4; nt++) {
        int cc = ns * 32 + nt * 8 + 2 * tig;
        float b0 = bias[cc], b1 = bias[cc + 1];
        if (mra < NN)
            *(float2*)&g_h[mra * HID + cc] = make_float2(acc[nt][0] + b0, acc[nt][1] + b1);
        if (mrb < NN)
            *(float2*)&g_h[mrb * HID + cc] = make_float2(acc[nt][2] + b0, acc[nt][3] + b1);
    }
}

// ---------------- layer linears: bf16 MMA + fused BN of previous layer -------
__global__ __launch_bounds__(256) void k_abde(
    const float* __restrict__ Aw, const float* __restrict__ Bw,
    const float* __restrict__ Dw, const float* __restrict__ Ew,
    const float* __restrict__ Ab, const float* __restrict__ Bb,
    const float* __restrict__ Db, const float* __restrict__ Eb,
    const float* __restrict__ pg, const float* __restrict__ pb,
    int l) {
    __shared__ unsigned Xh[64 * 32], Xl[64 * 32];
    __shared__ unsigned Wh[128 * 32], Wl[128 * 32];
    int t = threadIdx.x;
    int m0 = blockIdx.x * 64;
    const float invN = 1.f / (float)NN;

    for (int idx = t; idx < 64 * 16; idx += 256) {
        int r = idx >> 4, c4 = (idx & 15) * 4;
        int m = m0 + r;
        float4 v = make_float4(0.f, 0.f, 0.f, 0.f);
        if (m < NN) {
            v = *(const float4*)&g_h[m * HID + c4];
            if (l > 0) {
                const float* st = g_stats[l - 1];
                float4 hp = *(const float4*)&g_hp[m * HID + c4];
                #pragma unroll
                for (int j = 0; j < 4; j++) {
                    int c = c4 + j;
                    float mu  = st[c] * invN;
                    float var = st[HID + c] * invN - mu * mu;
                    float hpv = (j == 0) ? hp.x : (j == 1) ? hp.y : (j == 2) ? hp.z : hp.w;
                    float xn  = (hpv - mu) * rsqrtf(var + 1e-5f);
                    float vv  = fmaxf(pg[c] * xn + pb[c], 0.f);
                    if (j == 0) v.x += vv; else if (j == 1) v.y += vv;
                    else if (j == 2) v.z += vv; else v.w += vv;
                }
                *(float4*)&g_h[m * HID + c4] = v;
            }
        }
        int kp0 = c4 >> 1;
        unsigned hw, lw;
        int swz = (r & 7) << 2;
        split_pair(v.x, v.y, hw, lw);
        Xh[r * 32 + (kp0 ^ swz)] = hw;
        Xl[r * 32 + (kp0 ^ swz)] = lw;
        split_pair(v.z, v.w, hw, lw);
        Xh[r * 32 + ((kp0 + 1) ^ swz)] = hw;
        Xl[r * 32 + ((kp0 + 1) ^ swz)] = lw;
    }

    int lane = t & 31, w = t >> 5;
    int g = lane >> 2, tig = lane & 3;
    int mt = w & 3, ns = w >> 2;
    int r0 = mt * 16 + g, r1 = r0 + 8;

    #pragma unroll
    for (int half = 0; half < 2; half++) {
        for (int idx = t; idx < 32 * 128; idx += 256) {
            int kp = idx >> 7, c = idx & 127;
            int gc = half * 128 + c;
            int sel = gc >> 6, cc = gc & 63;
            const float* W = (sel == 0) ? Aw : (sel == 1) ? Bw : (sel == 2) ? Dw : Ew;
            float w0 = W[(2 * kp) * HID + cc];
            float w1 = W[(2 * kp + 1) * HID + cc];
            unsigned hw, lw;
            split_pair(w0, w1, hw, lw);
            int s = c * 32 + (kp ^ ((c & 7) << 2));
            Wh[s] = hw;
            Wl[s] = lw;
        }
        __syncthreads();

        float acc[8][4];
        #pragma unroll
        for (int i = 0; i < 8; i++)
            #pragma unroll
            for (int j = 0; j < 4; j++) acc[i][j] = 0.f;

        int swa0 = (r0 & 7) << 2, swa1 = (r1 & 7) << 2;
        #pragma unroll
        for (int ks = 0; ks < 4; ks++) {
            int kb = ks * 8;
            int kpa = kb + tig, kpb = kb + tig + 4;
            unsigned ah[4], al[4];
            int s0 = r0 * 32 + (kpa ^ swa0), s1 = r1 * 32 + (kpa ^ swa1);
            int s2 = r0 * 32 + (kpb ^ swa0), s3 = r1 * 32 + (kpb ^ swa1);
            ah[0] = Xh[s0]; ah[1] = Xh[s1]; ah[2] = Xh[s2]; ah[3] = Xh[s3];
            al[0] = Xl[s0]; al[1] = Xl[s1]; al[2] = Xl[s2]; al[3] = Xl[s3];
            #pragma unroll
            for (int nt = 0; nt < 8; nt++) {
                int c = ns * 64 + nt * 8 + g;
                int swc = (c & 7) << 2;
                int sb0 = c * 32 + (kpa ^ swc);
                int sb1 = c * 32 + (kpb ^ swc);
                unsigned bh[2] = {Wh[sb0], Wh[sb1]};
                unsigned bl[2] = {Wl[sb0], Wl[sb1]};
                mma_bf16(acc[nt], ah, bh);
                mma_bf16(acc[nt], al, bh);
                mma_bf16(acc[nt], ah, bl);
            }
        }

        int sel = half * 2 + ns;
        const float* bp = (sel == 0) ? Ab : (sel == 1) ? Bb : (sel == 2) ? Db : Eb;
        int mra = m0 + mt * 16 + g, mrb = mra + 8;
        if (sel == 0 || sel == 3) {
            float* Y = (sel == 0) ? g_A : g_E;
            #pragma unroll
            for (int nt = 0; nt < 8; nt++) {
                int cc = nt * 8 + 2 * tig;
                float b0v = bp[cc], b1v = bp[cc + 1];
                if (mra < NN)
                    *(float2*)&Y[mra * HID + cc] = make_float2(acc[nt][0] + b0v, acc[nt][1] + b1v);
                if (mrb < NN)
                    *(float2*)&Y[mrb * HID + cc] = make_float2(acc[nt][2] + b0v, acc[nt][3] + b1v);
            }
        } else {
            int boff = (sel == 1) ? 1 : 0;
            #pragma unroll
            for (int nt = 0; nt < 8; nt++) {
                int cc = nt * 8 + 2 * tig;
                float b0v = bp[cc], b1v = bp[cc + 1];
                if (mra < NN)
                    g_BD[mra * 64 + cc + boff] = pack_bf16x2(acc[nt][0] + b0v, acc[nt][1] + b1v);
                if (mrb < NN)
                    g_BD[mrb * 64 + cc + boff] = pack_bf16x2(acc[nt][2] + b0v, acc[nt][3] + b1v);
            }
        }
        __syncthreads();
    }
}

// ---------------- edge aggregation + fused BN stats (8-edge unrolled) ---------
__global__ __launch_bounds__(256) void k_agg(int l) {
    __shared__ float red_s[8][64], red_q[8][64];
    int w = threadIdx.x >> 5, lane = threadIdx.x & 31;
    int base = (blockIdx.x * 8 + w) * 4;
    float sx = 0.f, sy = 0.f, qx = 0.f, qy = 0.f;
    #pragma unroll 1
    for (int i = 0; i < 4; i++) {
        int gw = base + i;
        if (gw >= NN) break;
        int s0 = g_offs[gw], s1 = g_offs[gw + 1];
        int off = gw * HID + lane * 2;
        float2 el = *(const float2*)&g_E[off];
        float nx = 0.f, ny = 0.f, dx = 0.f, dy = 0.f;
        int k = s0;
        for (; k + 7 < s1; k += 8) {
            int sidx[8];
            uint2 v[8];
            #pragma unroll
            for (int j = 0; j < 8; j++) sidx[j] = g_csr[k + j];
            #pragma unroll
            for (int j = 0; j < 8; j++) v[j] = *(const uint2*)&g_BD[sidx[j] * 64 + lane * 2];
            #pragma unroll
            for (int j = 0; j < 8; j++) {
                float2 d = unpack_bf16x2(v[j].x), b = unpack_bf16x2(v[j].y);
                float gx = sigmoid_fast(d.x + el.x);
                float gy = sigmoid_fast(d.y + el.y);
                nx += gx * b.x; ny += gy * b.y;
                dx += gx;       dy += gy;
            }
        }
        for (; k + 3 < s1; k += 4) {
            int sidx[4];
            uint2 v[4];
            #pragma unroll
            for (int j = 0; j < 4; j++) sidx[j] = g_csr[k + j];
            #pragma unroll
            for (int j = 0; j < 4; j++) v[j] = *(const uint2*)&g_BD[sidx[j] * 64 + lane * 2];
            #pragma unroll
            for (int j = 0; j < 4; j++) {
                float2 d = unpack_bf16x2(v[j].x), b = unpack_bf16x2(v[j].y);
                float gx = sigmoid_fast(d.x + el.x);
                float gy = sigmoid_fast(d.y + el.y);
                nx += gx * b.x; ny += gy * b.y;
                dx += gx;       dy += gy;
            }
        }
        for (; k < s1; k++) {
            int sa = g_csr[k];
            uint2 va = *(const uint2*)&g_BD[sa * 64 + lane * 2];
            float2 d = unpack_bf16x2(va.x), b = unpack_bf16x2(va.y);
            float gx = sigmoid_fast(d.x + el.x);
            float gy = sigmoid_fast(d.y + el.y);
            nx += gx * b.x; ny += gy * b.y;
            dx += gx;       dy += gy;
        }
        float2 aa = *(const float2*)&g_A[off];
        float ox = aa.x + nx / (dx + 1e-6f);
        float oy = aa.y + ny / (dy + 1e-6f);
        *(float2*)&g_hp[off] = make_float2(ox, oy);
        sx += ox; sy += oy; qx += ox * ox; qy += oy * oy;
    }
    red_s[w][lane * 2] = sx;  red_s[w][lane * 2 + 1] = sy;
    red_q[w][lane * 2] = qx;  red_q[w][lane * 2 + 1] = qy;
    __syncthreads();
    int t = threadIdx.x;
    if (t < 64) {
        float s = 0.f, q = 0.f;
        #pragma unroll
        for (int ww = 0; ww < 8; ww++) { s += red_s[ww][t]; q += red_q[ww][t]; }
        atomicAdd(&g_stats[l][t], s);
        atomicAdd(&g_stats[l][HID + t], q);
    }
}

// ---------------- final BN/ReLU/residual -> d_out -----------------------------
__global__ __launch_bounds__(256) void k_bn_final(const float* __restrict__ gamma,
                                                  const float* __restrict__ beta,
                                                  float* __restrict__ out) {
    int idx = blockIdx.x * blockDim.x + threadIdx.x;
    if (idx >= NN * HID) return;
    int c = idx & 63;
    const float* st = g_stats[NL - 1];
    const float invN = 1.f / (float)NN;
    float mu  = st[c] * invN;
    float var = st[HID + c] * invN - mu * mu;
    float xn = (g_hp[idx] - mu) * rsqrtf(var + 1e-5f);
    float v = fmaxf(gamma[c] * xn + beta[c], 0.f);
    out[idx] = g_h[idx] + v;
}

// ---------------- launch ------------------------------------------------------
extern "C" void kernel_launch(void* const* d_in, const int* in_sizes, int n_in,
                              void* d_out, int out_size) {
    const float* feature = (const float*)d_in[0];
    const int*   ei      = (const int*)d_in[1];     // int32 (JAX x64 disabled)
    const float* emb_w   = (const float*)d_in[2];
    const float* emb_b   = (const float*)d_in[3];
    const float* Aw      = (const float*)d_in[4];
    const float* Ab      = (const float*)d_in[5];
    const float* Bw      = (const float*)d_in[6];
    const float* Bb      = (const float*)d_in[7];
    const float* Dw      = (const float*)d_in[8];
    const float* Db      = (const float*)d_in[9];
    const float* Ew      = (const float*)d_in[10];
    const float* Eb      = (const float*)d_in[11];
    const float* gamma   = (const float*)d_in[12];
    const float* beta    = (const float*)d_in[13];
    float* out = (float*)d_out;

    k_clear_deg<<<(NN + 255) / 256, 256>>>();
    k_hist<<<(EE / 2 + 255) / 256, 256>>>(ei);
    k_scan1<<<1, 256>>>();
    k_offs<<<SCAN_B, 256>>>();
    k_scatter<<<(EE / 2 + 255) / 256, 256>>>(ei);

    k_embed<<<(NN + 63) / 64, 256>>>(feature, emb_w, emb_b);

    for (int l = 0; l < NL; l++) {
        const float* pg = (l > 0) ? gamma + (l - 1) * HID : gamma;
        const float* pb = (l > 0) ? beta  + (l - 1) * HID : beta;
        k_abde<<<(NN + 63) / 64, 256>>>(
            Aw + l * HID * HID, Bw + l * HID * HID,
            Dw + l * HID * HID, Ew + l * HID * HID,
            Ab + l * HID, Bb + l * HID, Db + l * HID, Eb + l * HID,
            pg, pb, l);
        k_agg<<<(NN + 31) / 32, 256>>>(l);
    }
    k_bn_final<<<(NN * HID + 255) / 256, 256>>>(gamma + (NL - 1) * HID,
                                                beta + (NL - 1) * HID, out);
}

// round 11
// speedup vs baseline: 1.8309x; 1.0675x over previous
#include <cuda_runtime.h>
#include <cuda_bf16.h>

#define NN 50000
#define EE 1000000
#define IN_DIM 128
#define HID 64
#define NL 4
#define SCAN_B 196   // ceil(NN/256)

// ---------------- scratch (static device globals; no allocation) -------------
__device__ float    g_h[NN * HID];     // node features (residual-applied)
__device__ float    g_hp[NN * HID];    // pre-BN layer output
__device__ float    g_A[NN * HID];
__device__ float    g_E[NN * HID];
__device__ unsigned g_BD[NN * 64];     // interleaved: even word = D pack, odd = B pack
__device__ int      g_deg[NN];
__device__ int      g_offs[NN + 1];
__device__ int      g_cursor[NN];
__device__ int      g_csr[EE];
__device__ float    g_stats[NL][2 * HID];  // per-layer: sum, sumsq
__device__ int      g_bpre[256];
// pre-split weights, swizzled smem layout: [layer][c*32 + (kp ^ ((c&7)<<2))]
__device__ unsigned g_Wh[NL * 256 * 32];
__device__ unsigned g_Wl[NL * 256 * 32];

__device__ __forceinline__ unsigned pack_bf16x2(float a, float b) {
    __nv_bfloat162 h = __floats2bfloat162_rn(a, b);
    return *reinterpret_cast<unsigned*>(&h);
}
__device__ __forceinline__ float2 unpack_bf16x2(unsigned u) {
    __nv_bfloat162 h = *reinterpret_cast<__nv_bfloat162*>(&u);
    return __bfloat1622float2(h);
}
__device__ __forceinline__ float sigmoid_fast(float x) {
    float t;
    asm("tanh.approx.f32 %0, %1;" : "=f"(t) : "f"(0.5f * x));
    return fmaf(t, 0.5f, 0.5f);
}
// split consecutive-k pair into bf16 hi-word and lo-word
__device__ __forceinline__ void split_pair(float x0, float x1,
                                           unsigned& hw, unsigned& lw) {
    __nv_bfloat16 h0 = __float2bfloat16(x0);
    __nv_bfloat16 h1 = __float2bfloat16(x1);
    float r0 = x0 - __bfloat162float(h0);
    float r1 = x1 - __bfloat162float(h1);
    __nv_bfloat16 l0 = __float2bfloat16(r0);
    __nv_bfloat16 l1 = __float2bfloat16(r1);
    hw = (unsigned)__bfloat16_as_ushort(h0) | ((unsigned)__bfloat16_as_ushort(h1) << 16);
    lw = (unsigned)__bfloat16_as_ushort(l0) | ((unsigned)__bfloat16_as_ushort(l1) << 16);
}
__device__ __forceinline__ void mma_bf16(float* d, const unsigned* a, const unsigned* b) {
    asm("mma.sync.aligned.m16n8k16.row.col.f32.bf16.bf16.f32 "
        "{%0,%1,%2,%3}, {%4,%5,%6,%7}, {%8,%9}, {%0,%1,%2,%3};"
        : "+f"(d[0]), "+f"(d[1]), "+f"(d[2]), "+f"(d[3])
        : "r"(a[0]), "r"(a[1]), "r"(a[2]), "r"(a[3]), "r"(b[0]), "r"(b[1]));
}

// ---------------- init: clear deg/stats + pre-split all layer weights ---------
__global__ void k_init(const float* __restrict__ Aw, const float* __restrict__ Bw,
                       const float* __restrict__ Dw, const float* __restrict__ Ew) {
    int b = blockIdx.x, t = threadIdx.x;
    int i = b * 256 + t;
    if (i < NN) g_deg[i] = 0;
    if (i < NL * 2 * HID) ((float*)g_stats)[i] = 0.f;
    if (b < NL) {   // blocks 0..3: split layer b's weights into swizzled layout
        for (int idx = t; idx < 256 * 32; idx += 256) {
            int c = idx >> 5, kp = idx & 31;
            int sel = c >> 6, cc = c & 63;
            const float* W = (sel == 0) ? Aw : (sel == 1) ? Bw : (sel == 2) ? Dw : Ew;
            float w0 = W[b * HID * HID + (2 * kp) * HID + cc];
            float w1 = W[b * HID * HID + (2 * kp + 1) * HID + cc];
            unsigned hw, lw;
            split_pair(w0, w1, hw, lw);
            int s = b * 8192 + c * 32 + (kp ^ ((c & 7) << 2));
            g_Wh[s] = hw;
            g_Wl[s] = lw;
        }
    }
}

__global__ void k_hist(const int* __restrict__ ei) {
    int e = (blockIdx.x * blockDim.x + threadIdx.x) * 2;
    if (e < EE) {
        int2 d2 = *(const int2*)&ei[EE + e];
        if (d2.x >= 0 && d2.x < NN) atomicAdd(&g_deg[d2.x], 1);
        if (d2.y >= 0 && d2.y < NN) atomicAdd(&g_deg[d2.y], 1);
    }
}

// merged: per-chunk sums (256 nodes each) + exclusive scan, single block
__global__ void k_scan1() {
    __shared__ int sums[224];
    __shared__ int ws[8];
    int t = threadIdx.x, lane = t & 31, w = t >> 5;
    for (int c = t; c < 224; c += 256) sums[c] = 0;
    __syncthreads();
    for (int c = w; c < SCAN_B; c += 8) {
        int s = 0;
        #pragma unroll
        for (int i = 0; i < 8; i++) {
            int idx = c * 256 + i * 32 + lane;
            s += (idx < NN) ? g_deg[idx] : 0;
        }
        #pragma unroll
        for (int o = 16; o; o >>= 1) s += __shfl_down_sync(0xffffffffu, s, o);
        if (lane == 0) sums[c] = s;
    }
    __syncthreads();
    int v = (t < SCAN_B) ? sums[t] : 0;
    int x = v;
    #pragma unroll
    for (int o = 1; o < 32; o <<= 1) {
        int y = __shfl_up_sync(0xffffffffu, x, o);
        if (lane >= o) x += y;
    }
    if (lane == 31) ws[w] = x;
    __syncthreads();
    if (t < 8) {
        int q = ws[t];
        #pragma unroll
        for (int o = 1; o < 8; o <<= 1) {
            int y = __shfl_up_sync(0xffu, q, o);
            if (t >= o) q += y;
        }
        ws[t] = q;
    }
    __syncthreads();
    int incl = x + (w ? ws[w - 1] : 0);
    g_bpre[t] = incl - v;
}

__global__ void k_offs() {
    __shared__ int ws[8];
    int t = threadIdx.x, b = blockIdx.x;
    int i = b * 256 + t;
    int v = (i < NN) ? g_deg[i] : 0;
    int lane = t & 31, wid = t >> 5;
    int x = v;
    #pragma unroll
    for (int o = 1; o < 32; o <<= 1) {
        int y = __shfl_up_sync(0xffffffffu, x, o);
        if (lane >= o) x += y;
    }
    if (lane == 31) ws[wid] = x;
    __syncthreads();
    if (t < 8) {
        int w = ws[t];
        #pragma unroll
        for (int o = 1; o < 8; o <<= 1) {
            int y = __shfl_up_sync(0xffu, w, o);
            if (t >= o) w += y;
        }
        ws[t] = w;
    }
    __syncthreads();
    int incl = x + (wid ? ws[wid - 1] : 0);
    int base = g_bpre[b];
    if (i < NN) {
        g_offs[i + 1] = base + incl;
        g_cursor[i]   = base + incl - v;
    }
    if (i == 0) g_offs[0] = 0;
}

__global__ void k_scatter(const int* __restrict__ ei) {
    int e = (blockIdx.x * blockDim.x + threadIdx.x) * 2;
    if (e < EE) {
        int2 s2 = *(const int2*)&ei[e];
        int2 d2 = *(const int2*)&ei[EE + e];
        if (d2.x >= 0 && d2.x < NN) {
            int pos = atomicAdd(&g_cursor[d2.x], 1);
            if (pos >= 0 && pos < EE) g_csr[pos] = s2.x;
        }
        if (d2.y >= 0 && d2.y < NN) {
            int pos = atomicAdd(&g_cursor[d2.y], 1);
            if (pos >= 0 && pos < EE) g_csr[pos] = s2.y;
        }
    }
}

// ---------------- embed: bf16 MMA 3-term, 64 rows x 64 cols, K=128 -----------
__global__ __launch_bounds__(256) void k_embed(const float* __restrict__ X,
                                               const float* __restrict__ W,
                                               const float* __restrict__ bias) {
    __shared__ unsigned Xh[64 * 32], Xl[64 * 32];
    __shared__ unsigned Wh[64 * 32], Wl[64 * 32];
    int t = threadIdx.x;
    int m0 = blockIdx.x * 64;
    int lane = t & 31, w = t >> 5;
    int g = lane >> 2, tig = lane & 3;
    int mt = w & 3, ns = w >> 2;
    int r0 = mt * 16 + g, r1 = r0 + 8;

    float acc[4][4];
    #pragma unroll
    for (int i = 0; i < 4; i++)
        #pragma unroll
        for (int j = 0; j < 4; j++) acc[i][j] = 0.f;

    #pragma unroll
    for (int kc = 0; kc < 2; kc++) {
        for (int idx = t; idx < 64 * 16; idx += 256) {
            int r = idx >> 4, c4 = (idx & 15) * 4;
            int m = m0 + r;
            float4 v = make_float4(0.f, 0.f, 0.f, 0.f);
            if (m < NN) v = *(const float4*)&X[m * IN_DIM + kc * 64 + c4];
            int kp0 = c4 >> 1, swz = (r & 7) << 2;
            unsigned hw, lw;
            split_pair(v.x, v.y, hw, lw);
            Xh[r * 32 + (kp0 ^ swz)] = hw;
            Xl[r * 32 + (kp0 ^ swz)] = lw;
            split_pair(v.z, v.w, hw, lw);
            Xh[r * 32 + ((kp0 + 1) ^ swz)] = hw;
            Xl[r * 32 + ((kp0 + 1) ^ swz)] = lw;
        }
        for (int idx = t; idx < 32 * 64; idx += 256) {
            int kp = idx >> 6, c = idx & 63;
            float w0 = W[(kc * 64 + 2 * kp) * HID + c];
            float w1 = W[(kc * 64 + 2 * kp + 1) * HID + c];
            unsigned hw, lw;
            split_pair(w0, w1, hw, lw);
            int s = c * 32 + (kp ^ ((c & 7) << 2));
            Wh[s] = hw;
            Wl[s] = lw;
        }
        __syncthreads();

        int swa0 = (r0 & 7) << 2, swa1 = (r1 & 7) << 2;
        #pragma unroll
        for (int ks = 0; ks < 4; ks++) {
            int kpa = ks * 8 + tig, kpb = kpa + 4;
            unsigned ah[4], al[4];
            int s0 = r0 * 32 + (kpa ^ swa0), s1 = r1 * 32 + (kpa ^ swa1);
            int s2 = r0 * 32 + (kpb ^ swa0), s3 = r1 * 32 + (kpb ^ swa1);
            ah[0] = Xh[s0]; ah[1] = Xh[s1]; ah[2] = Xh[s2]; ah[3] = Xh[s3];
            al[0] = Xl[s0]; al[1] = Xl[s1]; al[2] = Xl[s2]; al[3] = Xl[s3];
            #pragma unroll
            for (int nt = 0; nt < 4; nt++) {
                int c = ns * 32 + nt * 8 + g;
                int swc = (c & 7) << 2;
                int sb0 = c * 32 + (kpa ^ swc);
                int sb1 = c * 32 + (kpb ^ swc);
                unsigned bh[2] = {Wh[sb0], Wh[sb1]};
                unsigned bl[2] = {Wl[sb0], Wl[sb1]};
                mma_bf16(acc[nt], ah, bh);
                mma_bf16(acc[nt], al, bh);
                mma_bf16(acc[nt], ah, bl);
            }
        }
        __syncthreads();
    }

    int mra = m0 + mt * 16 + g, mrb = mra + 8;
    #pragma unroll
    for (int nt = 0; nt < 4; nt++) {
        int cc = ns * 32 + nt * 8 + 2 * tig;
        float b0 = bias[cc], b1 = bias[cc + 1];
        if (mra < NN)
            *(float2*)&g_h[mra * HID + cc] = make_float2(acc[nt][0] + b0, acc[nt][1] + b1);
        if (mrb < NN)
            *(float2*)&g_h[mrb * HID + cc] = make_float2(acc[nt][2] + b0, acc[nt][3] + b1);
    }
}

// ---------------- layer linears: bf16 MMA, pre-split weights, fused BN -------
__global__ __launch_bounds__(256) void k_abde(
    const float* __restrict__ Ab, const float* __restrict__ Bb,
    const float* __restrict__ Db, const float* __restrict__ Eb,
    const float* __restrict__ pg, const float* __restrict__ pb,
    int l) {
    __shared__ unsigned Xh[64 * 32], Xl[64 * 32];
    __shared__ unsigned Wh[128 * 32], Wl[128 * 32];
    int t = threadIdx.x;
    int m0 = blockIdx.x * 64;
    const float invN = 1.f / (float)NN;

    for (int idx = t; idx < 64 * 16; idx += 256) {
        int r = idx >> 4, c4 = (idx & 15) * 4;
        int m = m0 + r;
        float4 v = make_float4(0.f, 0.f, 0.f, 0.f);
        if (m < NN) {
            v = *(const float4*)&g_h[m * HID + c4];
            if (l > 0) {
                const float* st = g_stats[l - 1];
                float4 hp = *(const float4*)&g_hp[m * HID + c4];
                #pragma unroll
                for (int j = 0; j < 4; j++) {
                    int c = c4 + j;
                    float mu  = st[c] * invN;
                    float var = st[HID + c] * invN - mu * mu;
                    float hpv = (j == 0) ? hp.x : (j == 1) ? hp.y : (j == 2) ? hp.z : hp.w;
                    float xn  = (hpv - mu) * rsqrtf(var + 1e-5f);
                    float vv  = fmaxf(pg[c] * xn + pb[c], 0.f);
                    if (j == 0) v.x += vv; else if (j == 1) v.y += vv;
                    else if (j == 2) v.z += vv; else v.w += vv;
                }
                *(float4*)&g_h[m * HID + c4] = v;
            }
        }
        int kp0 = c4 >> 1;
        unsigned hw, lw;
        int swz = (r & 7) << 2;
        split_pair(v.x, v.y, hw, lw);
        Xh[r * 32 + (kp0 ^ swz)] = hw;
        Xl[r * 32 + (kp0 ^ swz)] = lw;
        split_pair(v.z, v.w, hw, lw);
        Xh[r * 32 + ((kp0 + 1) ^ swz)] = hw;
        Xl[r * 32 + ((kp0 + 1) ^ swz)] = lw;
    }

    int lane = t & 31, w = t >> 5;
    int g = lane >> 2, tig = lane & 3;
    int mt = w & 3, ns = w >> 2;
    int r0 = mt * 16 + g, r1 = r0 + 8;

    #pragma unroll
    for (int half = 0; half < 2; half++) {
        // stage W half: straight uint4 copy (layout already swizzled globally)
        {
            const uint4* srcH = (const uint4*)(g_Wh + l * 8192 + half * 4096);
            const uint4* srcL = (const uint4*)(g_Wl + l * 8192 + half * 4096);
            uint4* dstH = (uint4*)Wh;
            uint4* dstL = (uint4*)Wl;
            #pragma unroll
            for (int j = 0; j < 4; j++) {
                dstH[t + j * 256] = srcH[t + j * 256];
                dstL[t + j * 256] = srcL[t + j * 256];
            }
        }
        __syncthreads();

        float acc[8][4];
        #pragma unroll
        for (int i = 0; i < 8; i++)
            #pragma unroll
            for (int j = 0; j < 4; j++) acc[i][j] = 0.f;

        int swa0 = (r0 & 7) << 2, swa1 = (r1 & 7) << 2;
        #pragma unroll
        for (int ks = 0; ks < 4; ks++) {
            int kb = ks * 8;
            int kpa = kb + tig, kpb = kb + tig + 4;
            unsigned ah[4], al[4];
            int s0 = r0 * 32 + (kpa ^ swa0), s1 = r1 * 32 + (kpa ^ swa1);
            int s2 = r0 * 32 + (kpb ^ swa0), s3 = r1 * 32 + (kpb ^ swa1);
            ah[0] = Xh[s0]; ah[1] = Xh[s1]; ah[2] = Xh[s2]; ah[3] = Xh[s3];
            al[0] = Xl[s0]; al[1] = Xl[s1]; al[2] = Xl[s2]; al[3] = Xl[s3];
            #pragma unroll
            for (int nt = 0; nt < 8; nt++) {
                int c = ns * 64 + nt * 8 + g;
                int swc = (c & 7) << 2;
                int sb0 = c * 32 + (kpa ^ swc);
                int sb1 = c * 32 + (kpb ^ swc);
                unsigned bh[2] = {Wh[sb0], Wh[sb1]};
                unsigned bl[2] = {Wl[sb0], Wl[sb1]};
                mma_bf16(acc[nt], ah, bh);
                mma_bf16(acc[nt], al, bh);
                mma_bf16(acc[nt], ah, bl);
            }
        }

        int sel = half * 2 + ns;
        const float* bp = (sel == 0) ? Ab : (sel == 1) ? Bb : (sel == 2) ? Db : Eb;
        int mra = m0 + mt * 16 + g, mrb = mra + 8;
        if (sel == 0 || sel == 3) {
            float* Y = (sel == 0) ? g_A : g_E;
            #pragma unroll
            for (int nt = 0; nt < 8; nt++) {
                int cc = nt * 8 + 2 * tig;
                float b0v = bp[cc], b1v = bp[cc + 1];
                if (mra < NN)
                    *(float2*)&Y[mra * HID + cc] = make_float2(acc[nt][0] + b0v, acc[nt][1] + b1v);
                if (mrb < NN)
                    *(float2*)&Y[mrb * HID + cc] = make_float2(acc[nt][2] + b0v, acc[nt][3] + b1v);
            }
        } else {
            int boff = (sel == 1) ? 1 : 0;
            #pragma unroll
            for (int nt = 0; nt < 8; nt++) {
                int cc = nt * 8 + 2 * tig;
                float b0v = bp[cc], b1v = bp[cc + 1];
                if (mra < NN)
                    g_BD[mra * 64 + cc + boff] = pack_bf16x2(acc[nt][0] + b0v, acc[nt][1] + b1v);
                if (mrb < NN)
                    g_BD[mrb * 64 + cc + boff] = pack_bf16x2(acc[nt][2] + b0v, acc[nt][3] + b1v);
            }
        }
        __syncthreads();
    }
}

// ---------------- edge aggregation + fused BN stats (8-edge unrolled) ---------
__global__ __launch_bounds__(256) void k_agg(int l) {
    __shared__ float red_s[8][64], red_q[8][64];
    int w = threadIdx.x >> 5, lane = threadIdx.x & 31;
    int base = (blockIdx.x * 8 + w) * 4;
    float sx = 0.f, sy = 0.f, qx = 0.f, qy = 0.f;
    #pragma unroll 1
    for (int i = 0; i < 4; i++) {
        int gw = base + i;
        if (gw >= NN) break;
        int s0 = g_offs[gw], s1 = g_offs[gw + 1];
        int off = gw * HID + lane * 2;
        float2 el = *(const float2*)&g_E[off];
        float nx = 0.f, ny = 0.f, dx = 0.f, dy = 0.f;
        int k = s0;
        for (; k + 7 < s1; k += 8) {
            int sidx[8];
            uint2 v[8];
            #pragma unroll
            for (int j = 0; j < 8; j++) sidx[j] = g_csr[k + j];
            #pragma unroll
            for (int j = 0; j < 8; j++) v[j] = *(const uint2*)&g_BD[sidx[j] * 64 + lane * 2];
            #pragma unroll
            for (int j = 0; j < 8; j++) {
                float2 d = unpack_bf16x2(v[j].x), b = unpack_bf16x2(v[j].y);
                float gx = sigmoid_fast(d.x + el.x);
                float gy = sigmoid_fast(d.y + el.y);
                nx += gx * b.x; ny += gy * b.y;
                dx += gx;       dy += gy;
            }
        }
        for (; k + 3 < s1; k += 4) {
            int sidx[4];
            uint2 v[4];
            #pragma unroll
            for (int j = 0; j < 4; j++) sidx[j] = g_csr[k + j];
            #pragma unroll
            for (int j = 0; j < 4; j++) v[j] = *(const uint2*)&g_BD[sidx[j] * 64 + lane * 2];
            #pragma unroll
            for (int j = 0; j < 4; j++) {
                float2 d = unpack_bf16x2(v[j].x), b = unpack_bf16x2(v[j].y);
                float gx = sigmoid_fast(d.x + el.x);
                float gy = sigmoid_fast(d.y + el.y);
                nx += gx * b.x; ny += gy * b.y;
                dx += gx;       dy += gy;
            }
        }
        for (; k < s1; k++) {
            int sa = g_csr[k];
            uint2 va = *(const uint2*)&g_BD[sa * 64 + lane * 2];
            float2 d = unpack_bf16x2(va.x), b = unpack_bf16x2(va.y);
            float gx = sigmoid_fast(d.x + el.x);
            float gy = sigmoid_fast(d.y + el.y);
            nx += gx * b.x; ny += gy * b.y;
            dx += gx;       dy += gy;
        }
        float2 aa = *(const float2*)&g_A[off];
        float ox = aa.x + nx / (dx + 1e-6f);
        float oy = aa.y + ny / (dy + 1e-6f);
        *(float2*)&g_hp[off] = make_float2(ox, oy);
        sx += ox; sy += oy; qx += ox * ox; qy += oy * oy;
    }
    red_s[w][lane * 2] = sx;  red_s[w][lane * 2 + 1] = sy;
    red_q[w][lane * 2] = qx;  red_q[w][lane * 2 + 1] = qy;
    __syncthreads();
    int t = threadIdx.x;
    if (t < 64) {
        float s = 0.f, q = 0.f;
        #pragma unroll
        for (int ww = 0; ww < 8; ww++) { s += red_s[ww][t]; q += red_q[ww][t]; }
        atomicAdd(&g_stats[l][t], s);
        atomicAdd(&g_stats[l][HID + t], q);
    }
}

// ---------------- final BN/ReLU/residual -> d_out -----------------------------
__global__ __launch_bounds__(256) void k_bn_final(const float* __restrict__ gamma,
                                                  const float* __restrict__ beta,
                                                  float* __restrict__ out) {
    int idx = blockIdx.x * blockDim.x + threadIdx.x;
    if (idx >= NN * HID) return;
    int c = idx & 63;
    const float* st = g_stats[NL - 1];
    const float invN = 1.f / (float)NN;
    float mu  = st[c] * invN;
    float var = st[HID + c] * invN - mu * mu;
    float xn = (g_hp[idx] - mu) * rsqrtf(var + 1e-5f);
    float v = fmaxf(gamma[c] * xn + beta[c], 0.f);
    out[idx] = g_h[idx] + v;
}

// ---------------- launch ------------------------------------------------------
extern "C" void kernel_launch(void* const* d_in, const int* in_sizes, int n_in,
                              void* d_out, int out_size) {
    const float* feature = (const float*)d_in[0];
    const int*   ei      = (const int*)d_in[1];     // int32 (JAX x64 disabled)
    const float* emb_w   = (const float*)d_in[2];
    const float* emb_b   = (const float*)d_in[3];
    const float* Aw      = (const float*)d_in[4];
    const float* Ab      = (const float*)d_in[5];
    const float* Bw      = (const float*)d_in[6];
    const float* Bb      = (const float*)d_in[7];
    const float* Dw      = (const float*)d_in[8];
    const float* Db      = (const float*)d_in[9];
    const float* Ew      = (const float*)d_in[10];
    const float* Eb      = (const float*)d_in[11];
    const float* gamma   = (const float*)d_in[12];
    const float* beta    = (const float*)d_in[13];
    float* out = (float*)d_out;

    k_init<<<SCAN_B, 256>>>(Aw, Bw, Dw, Ew);
    k_hist<<<(EE / 2 + 255) / 256, 256>>>(ei);
    k_scan1<<<1, 256>>>();
    k_offs<<<SCAN_B, 256>>>();
    k_scatter<<<(EE / 2 + 255) / 256, 256>>>(ei);

    k_embed<<<(NN + 63) / 64, 256>>>(feature, emb_w, emb_b);

    for (int l = 0; l < NL; l++) {
        const float* pg = (l > 0) ? gamma + (l - 1) * HID : gamma;
        const float* pb = (l > 0) ? beta  + (l - 1) * HID : beta;
        k_abde<<<(NN + 63) / 64, 256>>>(
            Ab + l * HID, Bb + l * HID, Db + l * HID, Eb + l * HID,
            pg, pb, l);
        k_agg<<<(NN + 31) / 32, 256>>>(l);
    }
    k_bn_final<<<(NN * HID + 255) / 256, 256>>>(gamma + (NL - 1) * HID,
                                                beta + (NL - 1) * HID, out);
}

// round 12
// speedup vs baseline: 1.9127x; 1.0447x over previous
#include <cuda_runtime.h>
#include <cuda_bf16.h>

#define NN 50000
#define EE 1000000
#define IN_DIM 128
#define HID 64
#define NL 4
#define SCAN_B 196   // ceil(NN/256)

// ---------------- host-side stream/events (created pre-main, no device mem in launch)
struct HxStreams {
    cudaStream_t s1;
    cudaEvent_t ev_fork, ev_join;
    HxStreams() {
        cudaStreamCreateWithFlags(&s1, cudaStreamNonBlocking);
        cudaEventCreateWithFlags(&ev_fork, cudaEventDisableTiming);
        cudaEventCreateWithFlags(&ev_join, cudaEventDisableTiming);
    }
};
static HxStreams g_hx;

// ---------------- scratch (static device globals; no allocation) -------------
__device__ float    g_h[NN * HID];     // node features (residual-applied)
__device__ float    g_hp[NN * HID];    // pre-BN layer output
__device__ float    g_A[NN * HID];
__device__ float    g_E[NN * HID];
__device__ unsigned g_BD[NN * 64];     // interleaved: even word = D pack, odd = B pack
__device__ int      g_deg[NN];
__device__ int      g_offs[NN + 1];
__device__ int      g_cursor[NN];
__device__ int      g_csr[EE];
__device__ float    g_stats[NL][2 * HID];  // per-layer: sum, sumsq
__device__ int      g_bpre[256];
// pre-split weights, swizzled smem layout: [layer][c*32 + (kp ^ ((c&7)<<2))]
__device__ unsigned g_Wh[NL * 256 * 32];
__device__ unsigned g_Wl[NL * 256 * 32];

__device__ __forceinline__ unsigned pack_bf16x2(float a, float b) {
    __nv_bfloat162 h = __floats2bfloat162_rn(a, b);
    return *reinterpret_cast<unsigned*>(&h);
}
__device__ __forceinline__ float2 unpack_bf16x2(unsigned u) {
    __nv_bfloat162 h = *reinterpret_cast<__nv_bfloat162*>(&u);
    return __bfloat1622float2(h);
}
__device__ __forceinline__ float sigmoid_fast(float x) {
    float t;
    asm("tanh.approx.f32 %0, %1;" : "=f"(t) : "f"(0.5f * x));
    return fmaf(t, 0.5f, 0.5f);
}
__device__ __forceinline__ void split_pair(float x0, float x1,
                                           unsigned& hw, unsigned& lw) {
    __nv_bfloat16 h0 = __float2bfloat16(x0);
    __nv_bfloat16 h1 = __float2bfloat16(x1);
    float r0 = x0 - __bfloat162float(h0);
    float r1 = x1 - __bfloat162float(h1);
    __nv_bfloat16 l0 = __float2bfloat16(r0);
    __nv_bfloat16 l1 = __float2bfloat16(r1);
    hw = (unsigned)__bfloat16_as_ushort(h0) | ((unsigned)__bfloat16_as_ushort(h1) << 16);
    lw = (unsigned)__bfloat16_as_ushort(l0) | ((unsigned)__bfloat16_as_ushort(l1) << 16);
}
__device__ __forceinline__ void mma_bf16(float* d, const unsigned* a, const unsigned* b) {
    asm("mma.sync.aligned.m16n8k16.row.col.f32.bf16.bf16.f32 "
        "{%0,%1,%2,%3}, {%4,%5,%6,%7}, {%8,%9}, {%0,%1,%2,%3};"
        : "+f"(d[0]), "+f"(d[1]), "+f"(d[2]), "+f"(d[3])
        : "r"(a[0]), "r"(a[1]), "r"(a[2]), "r"(a[3]), "r"(b[0]), "r"(b[1]));
}

// ---------------- s0 head: weight split + stats clear -------------------------
__global__ void k_wsplit(const float* __restrict__ Aw, const float* __restrict__ Bw,
                         const float* __restrict__ Dw, const float* __restrict__ Ew) {
    int b = blockIdx.x, t = threadIdx.x;
    int i = b * 256 + t;
    if (i < NL * 2 * HID) ((float*)g_stats)[i] = 0.f;
    for (int idx = t; idx < 256 * 32; idx += 256) {
        int c = idx >> 5, kp = idx & 31;
        int sel = c >> 6, cc = c & 63;
        const float* W = (sel == 0) ? Aw : (sel == 1) ? Bw : (sel == 2) ? Dw : Ew;
        float w0 = W[b * HID * HID + (2 * kp) * HID + cc];
        float w1 = W[b * HID * HID + (2 * kp + 1) * HID + cc];
        unsigned hw, lw;
        split_pair(w0, w1, hw, lw);
        int s = b * 8192 + c * 32 + (kp ^ ((c & 7) << 2));
        g_Wh[s] = hw;
        g_Wl[s] = lw;
    }
}

// ---------------- s1 chain: CSR build -----------------------------------------
__global__ void k_cleardeg() {
    int i = blockIdx.x * blockDim.x + threadIdx.x;
    if (i < NN) g_deg[i] = 0;
}

__global__ void k_hist(const int* __restrict__ ei) {
    int e = (blockIdx.x * blockDim.x + threadIdx.x) * 4;
    if (e < EE) {
        int4 d4 = *(const int4*)&ei[EE + e];
        if (d4.x >= 0 && d4.x < NN) atomicAdd(&g_deg[d4.x], 1);
        if (d4.y >= 0 && d4.y < NN) atomicAdd(&g_deg[d4.y], 1);
        if (d4.z >= 0 && d4.z < NN) atomicAdd(&g_deg[d4.z], 1);
        if (d4.w >= 0 && d4.w < NN) atomicAdd(&g_deg[d4.w], 1);
    }
}

__global__ void k_scan1() {
    __shared__ int sums[224];
    __shared__ int ws[8];
    int t = threadIdx.x, lane = t & 31, w = t >> 5;
    for (int c = t; c < 224; c += 256) sums[c] = 0;
    __syncthreads();
    for (int c = w; c < SCAN_B; c += 8) {
        int s = 0;
        #pragma unroll
        for (int i = 0; i < 8; i++) {
            int idx = c * 256 + i * 32 + lane;
            s += (idx < NN) ? g_deg[idx] : 0;
        }
        #pragma unroll
        for (int o = 16; o; o >>= 1) s += __shfl_down_sync(0xffffffffu, s, o);
        if (lane == 0) sums[c] = s;
    }
    __syncthreads();
    int v = (t < SCAN_B) ? sums[t] : 0;
    int x = v;
    #pragma unroll
    for (int o = 1; o < 32; o <<= 1) {
        int y = __shfl_up_sync(0xffffffffu, x, o);
        if (lane >= o) x += y;
    }
    if (lane == 31) ws[w] = x;
    __syncthreads();
    if (t < 8) {
        int q = ws[t];
        #pragma unroll
        for (int o = 1; o < 8; o <<= 1) {
            int y = __shfl_up_sync(0xffu, q, o);
            if (t >= o) q += y;
        }
        ws[t] = q;
    }
    __syncthreads();
    int incl = x + (w ? ws[w - 1] : 0);
    g_bpre[t] = incl - v;
}

__global__ void k_offs() {
    __shared__ int ws[8];
    int t = threadIdx.x, b = blockIdx.x;
    int i = b * 256 + t;
    int v = (i < NN) ? g_deg[i] : 0;
    int lane = t & 31, wid = t >> 5;
    int x = v;
    #pragma unroll
    for (int o = 1; o < 32; o <<= 1) {
        int y = __shfl_up_sync(0xffffffffu, x, o);
        if (lane >= o) x += y;
    }
    if (lane == 31) ws[wid] = x;
    __syncthreads();
    if (t < 8) {
        int w = ws[t];
        #pragma unroll
        for (int o = 1; o < 8; o <<= 1) {
            int y = __shfl_up_sync(0xffu, w, o);
            if (t >= o) w += y;
        }
        ws[t] = w;
    }
    __syncthreads();
    int incl = x + (wid ? ws[wid - 1] : 0);
    int base = g_bpre[b];
    if (i < NN) {
        g_offs[i + 1] = base + incl;
        g_cursor[i]   = base + incl - v;
    }
    if (i == 0) g_offs[0] = 0;
}

__global__ void k_scatter(const int* __restrict__ ei) {
    int e = (blockIdx.x * blockDim.x + threadIdx.x) * 4;
    if (e < EE) {
        int4 s4 = *(const int4*)&ei[e];
        int4 d4 = *(const int4*)&ei[EE + e];
        if (d4.x >= 0 && d4.x < NN) {
            int pos = atomicAdd(&g_cursor[d4.x], 1);
            if (pos >= 0 && pos < EE) g_csr[pos] = s4.x;
        }
        if (d4.y >= 0 && d4.y < NN) {
            int pos = atomicAdd(&g_cursor[d4.y], 1);
            if (pos >= 0 && pos < EE) g_csr[pos] = s4.y;
        }
        if (d4.z >= 0 && d4.z < NN) {
            int pos = atomicAdd(&g_cursor[d4.z], 1);
            if (pos >= 0 && pos < EE) g_csr[pos] = s4.z;
        }
        if (d4.w >= 0 && d4.w < NN) {
            int pos = atomicAdd(&g_cursor[d4.w], 1);
            if (pos >= 0 && pos < EE) g_csr[pos] = s4.w;
        }
    }
}

// ---------------- embed: bf16 MMA 3-term, 64 rows x 64 cols, K=128 -----------
__global__ __launch_bounds__(256) void k_embed(const float* __restrict__ X,
                                               const float* __restrict__ W,
                                               const float* __restrict__ bias) {
    __shared__ unsigned Xh[64 * 32], Xl[64 * 32];
    __shared__ unsigned Wh[64 * 32], Wl[64 * 32];
    int t = threadIdx.x;
    int m0 = blockIdx.x * 64;
    int lane = t & 31, w = t >> 5;
    int g = lane >> 2, tig = lane & 3;
    int mt = w & 3, ns = w >> 2;
    int r0 = mt * 16 + g, r1 = r0 + 8;

    float acc[4][4];
    #pragma unroll
    for (int i = 0; i < 4; i++)
        #pragma unroll
        for (int j = 0; j < 4; j++) acc[i][j] = 0.f;

    #pragma unroll
    for (int kc = 0; kc < 2; kc++) {
        for (int idx = t; idx < 64 * 16; idx += 256) {
            int r = idx >> 4, c4 = (idx & 15) * 4;
            int m = m0 + r;
            float4 v = make_float4(0.f, 0.f, 0.f, 0.f);
            if (m < NN) v = *(const float4*)&X[m * IN_DIM + kc * 64 + c4];
            int kp0 = c4 >> 1, swz = (r & 7) << 2;
            unsigned hw, lw;
            split_pair(v.x, v.y, hw, lw);
            Xh[r * 32 + (kp0 ^ swz)] = hw;
            Xl[r * 32 + (kp0 ^ swz)] = lw;
            split_pair(v.z, v.w, hw, lw);
            Xh[r * 32 + ((kp0 + 1) ^ swz)] = hw;
            Xl[r * 32 + ((kp0 + 1) ^ swz)] = lw;
        }
        for (int idx = t; idx < 32 * 64; idx += 256) {
            int kp = idx >> 6, c = idx & 63;
            float w0 = W[(kc * 64 + 2 * kp) * HID + c];
            float w1 = W[(kc * 64 + 2 * kp + 1) * HID + c];
            unsigned hw, lw;
            split_pair(w0, w1, hw, lw);
            int s = c * 32 + (kp ^ ((c & 7) << 2));
            Wh[s] = hw;
            Wl[s] = lw;
        }
        __syncthreads();

        int swa0 = (r0 & 7) << 2, swa1 = (r1 & 7) << 2;
        #pragma unroll
        for (int ks = 0; ks < 4; ks++) {
            int kpa = ks * 8 + tig, kpb = kpa + 4;
            unsigned ah[4], al[4];
            int s0 = r0 * 32 + (kpa ^ swa0), s1 = r1 * 32 + (kpa ^ swa1);
            int s2 = r0 * 32 + (kpb ^ swa0), s3 = r1 * 32 + (kpb ^ swa1);
            ah[0] = Xh[s0]; ah[1] = Xh[s1]; ah[2] = Xh[s2]; ah[3] = Xh[s3];
            al[0] = Xl[s0]; al[1] = Xl[s1]; al[2] = Xl[s2]; al[3] = Xl[s3];
            #pragma unroll
            for (int nt = 0; nt < 4; nt++) {
                int c = ns * 32 + nt * 8 + g;
                int swc = (c & 7) << 2;
                int sb0 = c * 32 + (kpa ^ swc);
                int sb1 = c * 32 + (kpb ^ swc);
                unsigned bh[2] = {Wh[sb0], Wh[sb1]};
                unsigned bl[2] = {Wl[sb0], Wl[sb1]};
                mma_bf16(acc[nt], ah, bh);
                mma_bf16(acc[nt], al, bh);
                mma_bf16(acc[nt], ah, bl);
            }
        }
        __syncthreads();
    }

    int mra = m0 + mt * 16 + g, mrb = mra + 8;
    #pragma unroll
    for (int nt = 0; nt < 4; nt++) {
        int cc = ns * 32 + nt * 8 + 2 * tig;
        float b0 = bias[cc], b1 = bias[cc + 1];
        if (mra < NN)
            *(float2*)&g_h[mra * HID + cc] = make_float2(acc[nt][0] + b0, acc[nt][1] + b1);
        if (mrb < NN)
            *(float2*)&g_h[mrb * HID + cc] = make_float2(acc[nt][2] + b0, acc[nt][3] + b1);
    }
}

// ---------------- layer linears: bf16 MMA, pre-split weights, fused BN -------
__global__ __launch_bounds__(256) void k_abde(
    const float* __restrict__ Ab, const float* __restrict__ Bb,
    const float* __restrict__ Db, const float* __restrict__ Eb,
    const float* __restrict__ pg, const float* __restrict__ pb,
    int l) {
    __shared__ unsigned Xh[64 * 32], Xl[64 * 32];
    __shared__ unsigned Wh[128 * 32], Wl[128 * 32];
    int t = threadIdx.x;
    int m0 = blockIdx.x * 64;
    const float invN = 1.f / (float)NN;

    for (int idx = t; idx < 64 * 16; idx += 256) {
        int r = idx >> 4, c4 = (idx & 15) * 4;
        int m = m0 + r;
        float4 v = make_float4(0.f, 0.f, 0.f, 0.f);
        if (m < NN) {
            v = *(const float4*)&g_h[m * HID + c4];
            if (l > 0) {
                const float* st = g_stats[l - 1];
                float4 hp = *(const float4*)&g_hp[m * HID + c4];
                #pragma unroll
                for (int j = 0; j < 4; j++) {
                    int c = c4 + j;
                    float mu  = st[c] * invN;
                    float var = st[HID + c] * invN - mu * mu;
                    float hpv = (j == 0) ? hp.x : (j == 1) ? hp.y : (j == 2) ? hp.z : hp.w;
                    float xn  = (hpv - mu) * rsqrtf(var + 1e-5f);
                    float vv  = fmaxf(pg[c] * xn + pb[c], 0.f);
                    if (j == 0) v.x += vv; else if (j == 1) v.y += vv;
                    else if (j == 2) v.z += vv; else v.w += vv;
                }
                *(float4*)&g_h[m * HID + c4] = v;
            }
        }
        int kp0 = c4 >> 1;
        unsigned hw, lw;
        int swz = (r & 7) << 2;
        split_pair(v.x, v.y, hw, lw);
        Xh[r * 32 + (kp0 ^ swz)] = hw;
        Xl[r * 32 + (kp0 ^ swz)] = lw;
        split_pair(v.z, v.w, hw, lw);
        Xh[r * 32 + ((kp0 + 1) ^ swz)] = hw;
        Xl[r * 32 + ((kp0 + 1) ^ swz)] = lw;
    }

    int lane = t & 31, w = t >> 5;
    int g = lane >> 2, tig = lane & 3;
    int mt = w & 3, ns = w >> 2;
    int r0 = mt * 16 + g, r1 = r0 + 8;

    #pragma unroll
    for (int half = 0; half < 2; half++) {
        {
            const uint4* srcH = (const uint4*)(g_Wh + l * 8192 + half * 4096);
            const uint4* srcL = (const uint4*)(g_Wl + l * 8192 + half * 4096);
            uint4* dstH = (uint4*)Wh;
            uint4* dstL = (uint4*)Wl;
            #pragma unroll
            for (int j = 0; j < 4; j++) {
                dstH[t + j * 256] = srcH[t + j * 256];
                dstL[t + j * 256] = srcL[t + j * 256];
            }
        }
        __syncthreads();

        float acc[8][4];
        #pragma unroll
        for (int i = 0; i < 8; i++)
            #pragma unroll
            for (int j = 0; j < 4; j++) acc[i][j] = 0.f;

        int swa0 = (r0 & 7) << 2, swa1 = (r1 & 7) << 2;
        #pragma unroll
        for (int ks = 0; ks < 4; ks++) {
            int kb = ks * 8;
            int kpa = kb + tig, kpb = kb + tig + 4;
            unsigned ah[4], al[4];
            int s0 = r0 * 32 + (kpa ^ swa0), s1 = r1 * 32 + (kpa ^ swa1);
            int s2 = r0 * 32 + (kpb ^ swa0), s3 = r1 * 32 + (kpb ^ swa1);
            ah[0] = Xh[s0]; ah[1] = Xh[s1]; ah[2] = Xh[s2]; ah[3] = Xh[s3];
            al[0] = Xl[s0]; al[1] = Xl[s1]; al[2] = Xl[s2]; al[3] = Xl[s3];
            #pragma unroll
            for (int nt = 0; nt < 8; nt++) {
                int c = ns * 64 + nt * 8 + g;
                int swc = (c & 7) << 2;
                int sb0 = c * 32 + (kpa ^ swc);
                int sb1 = c * 32 + (kpb ^ swc);
                unsigned bh[2] = {Wh[sb0], Wh[sb1]};
                unsigned bl[2] = {Wl[sb0], Wl[sb1]};
                mma_bf16(acc[nt], ah, bh);
                mma_bf16(acc[nt], al, bh);
                mma_bf16(acc[nt], ah, bl);
            }
        }

        int sel = half * 2 + ns;
        const float* bp = (sel == 0) ? Ab : (sel == 1) ? Bb : (sel == 2) ? Db : Eb;
        int mra = m0 + mt * 16 + g, mrb = mra + 8;
        if (sel == 0 || sel == 3) {
            float* Y = (sel == 0) ? g_A : g_E;
            #pragma unroll
            for (int nt = 0; nt < 8; nt++) {
                int cc = nt * 8 + 2 * tig;
                float b0v = bp[cc], b1v = bp[cc + 1];
                if (mra < NN)
                    *(float2*)&Y[mra * HID + cc] = make_float2(acc[nt][0] + b0v, acc[nt][1] + b1v);
                if (mrb < NN)
                    *(float2*)&Y[mrb * HID + cc] = make_float2(acc[nt][2] + b0v, acc[nt][3] + b1v);
            }
        } else {
            int boff = (sel == 1) ? 1 : 0;
            #pragma unroll
            for (int nt = 0; nt < 8; nt++) {
                int cc = nt * 8 + 2 * tig;
                float b0v = bp[cc], b1v = bp[cc + 1];
                if (mra < NN)
                    g_BD[mra * 64 + cc + boff] = pack_bf16x2(acc[nt][0] + b0v, acc[nt][1] + b1v);
                if (mrb < NN)
                    g_BD[mrb * 64 + cc + boff] = pack_bf16x2(acc[nt][2] + b0v, acc[nt][3] + b1v);
            }
        }
        __syncthreads();
    }
}

// ---------------- edge aggregation + fused BN stats (8-edge unrolled) ---------
__global__ __launch_bounds__(256) void k_agg(int l) {
    __shared__ float red_s[8][64], red_q[8][64];
    int w = threadIdx.x >> 5, lane = threadIdx.x & 31;
    int base = (blockIdx.x * 8 + w) * 4;
    float sx = 0.f, sy = 0.f, qx = 0.f, qy = 0.f;
    #pragma unroll 1
    for (int i = 0; i < 4; i++) {
        int gw = base + i;
        if (gw >= NN) break;
        int s0 = g_offs[gw], s1 = g_offs[gw + 1];
        int off = gw * HID + lane * 2;
        float2 el = *(const float2*)&g_E[off];
        float nx = 0.f, ny = 0.f, dx = 0.f, dy = 0.f;
        int k = s0;
        for (; k + 7 < s1; k += 8) {
            int sidx[8];
            uint2 v[8];
            #pragma unroll
            for (int j = 0; j < 8; j++) sidx[j] = g_csr[k + j];
            #pragma unroll
            for (int j = 0; j < 8; j++) v[j] = *(const uint2*)&g_BD[sidx[j] * 64 + lane * 2];
            #pragma unroll
            for (int j = 0; j < 8; j++) {
                float2 d = unpack_bf16x2(v[j].x), b = unpack_bf16x2(v[j].y);
                float gx = sigmoid_fast(d.x + el.x);
                float gy = sigmoid_fast(d.y + el.y);
                nx += gx * b.x; ny += gy * b.y;
                dx += gx;       dy += gy;
            }
        }
        for (; k + 3 < s1; k += 4) {
            int sidx[4];
            uint2 v[4];
            #pragma unroll
            for (int j = 0; j < 4; j++) sidx[j] = g_csr[k + j];
            #pragma unroll
            for (int j = 0; j < 4; j++) v[j] = *(const uint2*)&g_BD[sidx[j] * 64 + lane * 2];
            #pragma unroll
            for (int j = 0; j < 4; j++) {
                float2 d = unpack_bf16x2(v[j].x), b = unpack_bf16x2(v[j].y);
                float gx = sigmoid_fast(d.x + el.x);
                float gy = sigmoid_fast(d.y + el.y);
                nx += gx * b.x; ny += gy * b.y;
                dx += gx;       dy += gy;
            }
        }
        for (; k < s1; k++) {
            int sa = g_csr[k];
            uint2 va = *(const uint2*)&g_BD[sa * 64 + lane * 2];
            float2 d = unpack_bf16x2(va.x), b = unpack_bf16x2(va.y);
            float gx = sigmoid_fast(d.x + el.x);
            float gy = sigmoid_fast(d.y + el.y);
            nx += gx * b.x; ny += gy * b.y;
            dx += gx;       dy += gy;
        }
        float2 aa = *(const float2*)&g_A[off];
        float ox = aa.x + nx / (dx + 1e-6f);
        float oy = aa.y + ny / (dy + 1e-6f);
        *(float2*)&g_hp[off] = make_float2(ox, oy);
        sx += ox; sy += oy; qx += ox * ox; qy += oy * oy;
    }
    red_s[w][lane * 2] = sx;  red_s[w][lane * 2 + 1] = sy;
    red_q[w][lane * 2] = qx;  red_q[w][lane * 2 + 1] = qy;
    __syncthreads();
    int t = threadIdx.x;
    if (t < 64) {
        float s = 0.f, q = 0.f;
        #pragma unroll
        for (int ww = 0; ww < 8; ww++) { s += red_s[ww][t]; q += red_q[ww][t]; }
        atomicAdd(&g_stats[l][t], s);
        atomicAdd(&g_stats[l][HID + t], q);
    }
}

// ---------------- final BN/ReLU/residual -> d_out -----------------------------
__global__ __launch_bounds__(256) void k_bn_final(const float* __restrict__ gamma,
                                                  const float* __restrict__ beta,
                                                  float* __restrict__ out) {
    int idx = blockIdx.x * blockDim.x + threadIdx.x;
    if (idx >= NN * HID) return;
    int c = idx & 63;
    const float* st = g_stats[NL - 1];
    const float invN = 1.f / (float)NN;
    float mu  = st[c] * invN;
    float var = st[HID + c] * invN - mu * mu;
    float xn = (g_hp[idx] - mu) * rsqrtf(var + 1e-5f);
    float v = fmaxf(gamma[c] * xn + beta[c], 0.f);
    out[idx] = g_h[idx] + v;
}

// ---------------- launch ------------------------------------------------------
extern "C" void kernel_launch(void* const* d_in, const int* in_sizes, int n_in,
                              void* d_out, int out_size) {
    const float* feature = (const float*)d_in[0];
    const int*   ei      = (const int*)d_in[1];     // int32 (JAX x64 disabled)
    const float* emb_w   = (const float*)d_in[2];
    const float* emb_b   = (const float*)d_in[3];
    const float* Aw      = (const float*)d_in[4];
    const float* Ab      = (const float*)d_in[5];
    const float* Bw      = (const float*)d_in[6];
    const float* Bb      = (const float*)d_in[7];
    const float* Dw      = (const float*)d_in[8];
    const float* Db      = (const float*)d_in[9];
    const float* Ew      = (const float*)d_in[10];
    const float* Eb      = (const float*)d_in[11];
    const float* gamma   = (const float*)d_in[12];
    const float* beta    = (const float*)d_in[13];
    float* out = (float*)d_out;

    // fork: CSR build on side stream, GEMM chain on origin stream
    cudaEventRecord(g_hx.ev_fork, 0);
    cudaStreamWaitEvent(g_hx.s1, g_hx.ev_fork, 0);

    // s1: CSR build
    k_cleardeg<<<(NN + 255) / 256, 256, 0, g_hx.s1>>>();
    k_hist<<<(EE / 4 + 255) / 256, 256, 0, g_hx.s1>>>(ei);
    k_scan1<<<1, 256, 0, g_hx.s1>>>();
    k_offs<<<SCAN_B, 256, 0, g_hx.s1>>>();
    k_scatter<<<(EE / 4 + 255) / 256, 256, 0, g_hx.s1>>>(ei);
    cudaEventRecord(g_hx.ev_join, g_hx.s1);

    // s0: weight split -> embed -> abde(l=0)  (independent of CSR)
    k_wsplit<<<NL, 256>>>(Aw, Bw, Dw, Ew);
    k_embed<<<(NN + 63) / 64, 256>>>(feature, emb_w, emb_b);
    k_abde<<<(NN + 63) / 64, 256>>>(Ab, Bb, Db, Eb, gamma, beta, 0);

    // join: agg needs CSR
    cudaStreamWaitEvent(0, g_hx.ev_join, 0);
    k_agg<<<(NN + 31) / 32, 256>>>(0);

    for (int l = 1; l < NL; l++) {
        const float* pg = gamma + (l - 1) * HID;
        const float* pb = beta  + (l - 1) * HID;
        k_abde<<<(NN + 63) / 64, 256>>>(
            Ab + l * HID, Bb + l * HID, Db + l * HID, Eb + l * HID,
            pg, pb, l);
        k_agg<<<(NN + 31) / 32, 256>>>(l);
    }
    k_bn_final<<<(NN * HID + 255) / 256, 256>>>(gamma + (NL - 1) * HID,
                                                beta + (NL - 1) * HID, out);
}